// round 3
// baseline (speedup 1.0000x reference)
#include <cuda_runtime.h>
#include <math.h>

#define NS 16384          // samples
#define NB 100            // quadrature order
#define NQ 101            // quadrature points
#define HID 100           // hidden dim
#define ROWSK (NS * NQ)   // rows per network
#define TPB 320           // threads per block in mlp kernel

// ---------------- device globals (scratch; no allocations allowed) ----------
__device__ float g_ccw[NQ];        // Clenshaw-Curtis weights
__device__ float g_csc[NQ];        // (cos(j*pi/NB)+1)/2
__device__ float g_oh[3][2];       // h-MLP(0) outputs per network
__device__ float g_dz[3][ROWSK];   // per-row dz * ccw
__device__ float g_x2[NS];         // mono(0, x1) output

// ---------------- setup: CC quadrature (fp64, matches numpy) + oh constants --
__global__ void setup_kernel(const float* __restrict__ hb0,
                             const float* __restrict__ hW1,
                             const float* __restrict__ hb1,
                             const float* __restrict__ hW2,
                             const float* __restrict__ hb2,
                             const float* __restrict__ hW3,
                             const float* __restrict__ hb3)
{
    const double PI = 3.14159265358979323846;
    int t = threadIdx.x;

    if (t < NQ) {
        double acc = 0.0;
        for (int i = 0; i <= NB; i++) {
            double lij = cos((double)i * (double)t * PI / (double)NB);
            if (t == 0)  lij = 0.5;          // lam[:,0] = 0.5
            if (t == NB) lij *= 0.5;         // lam[:,-1] *= 0.5
            double Wi;
            if (i == 0)      Wi = 1.0;
            else if (i & 1)  Wi = 0.0;
            else             Wi = 2.0 / (1.0 - (double)i * (double)i);
            acc += lij * Wi;
        }
        g_ccw[t] = (float)(acc * 2.0 / (double)NB);
        g_csc[t] = (float)((cos((double)t * PI / (double)NB) + 1.0) * 0.5);
    }

    // oh_k = MLP_h(0): first hidden = relu(bias0)
    __shared__ float hA[HID], hB[HID];
    for (int k = 0; k < 3; k++) {
        if (t < HID) hA[t] = fmaxf(hb0[k * HID + t], 0.f);
        __syncthreads();
        if (t < HID) {
            float s = hb1[k * HID + t];
            for (int i = 0; i < HID; i++) s += hW1[(k * HID + t) * HID + i] * hA[i];
            hB[t] = fmaxf(s, 0.f);
        }
        __syncthreads();
        if (t < HID) {
            float s = hb2[k * HID + t];
            for (int i = 0; i < HID; i++) s += hW2[(k * HID + t) * HID + i] * hB[i];
            hA[t] = fmaxf(s, 0.f);
        }
        __syncthreads();
        if (t < 2) {
            float s = hb3[k * 2 + t];
            for (int i = 0; i < HID; i++) s += hW3[(k * 2 + t) * HID + i] * hA[i];
            g_oh[k][t] = s;
        }
        __syncthreads();
    }
}

// ---------------- main MLP kernel: one thread = one (n,k,j) row --------------
// shared: A[HID][TPB] activations, W1t/W2t transposed weights, small vectors
__global__ __launch_bounds__(TPB, 1)
void mlp_kernel(const float* __restrict__ xin, int kbase,
                const float* __restrict__ iW0, const float* __restrict__ ib0,
                const float* __restrict__ iW1, const float* __restrict__ ib1,
                const float* __restrict__ iW2, const float* __restrict__ ib2,
                const float* __restrict__ iW3, const float* __restrict__ ib3,
                float* __restrict__ dzbase)
{
    extern __shared__ float smem[];
    float* A   = smem;                      // HID*TPB
    float* W1t = A   + HID * TPB;           // HID*HID (W1t[i*HID+j] = W1[j][i])
    float* W2t = W1t + HID * HID;
    float* w0  = W2t + HID * HID;           // HID
    float* b0  = w0 + HID;
    float* b1  = b0 + HID;
    float* b2  = b1 + HID;
    float* w3  = b2 + HID;                  // HID

    const int tid = threadIdx.x;
    const int k   = kbase + blockIdx.y;

    // stage (transposed) weights
    for (int idx = tid; idx < HID * HID; idx += TPB) {
        int j = idx / HID, i = idx % HID;
        W1t[i * HID + j] = iW1[(k * HID + j) * HID + i];
        W2t[i * HID + j] = iW2[(k * HID + j) * HID + i];
    }
    for (int idx = tid; idx < HID; idx += TPB) {
        w0[idx] = iW0[(k * HID + idx) * 3];   // only input column 0 matters (h == 0)
        b0[idx] = ib0[k * HID + idx];
        b1[idx] = ib1[k * HID + idx];
        b2[idx] = ib2[k * HID + idx];
        w3[idx] = iW3[k * HID + idx];
    }
    __syncthreads();

    int row = blockIdx.x * TPB + tid;
    bool active = row < ROWSK;
    int n = active ? row / NQ : 0;
    int j = active ? row % NQ : 0;

    float x = xin[n];
    float s = x * g_csc[j];

    // layer 0: scalar -> HID
    #pragma unroll 4
    for (int i = 0; i < HID; i++)
        A[i * TPB + tid] = fmaxf(fmaf(w0[i], s, b0[i]), 0.f);

    // layers 1 and 2: HID -> HID, activations in shared, 100 reg accumulators
    const float* Wp = W1t;
    const float* bp = b1;
    for (int L = 0; L < 2; L++) {
        float acc[HID];
        #pragma unroll
        for (int jc = 0; jc < 5; jc++)
            #pragma unroll
            for (int t = 0; t < 20; t++)
                acc[jc * 20 + t] = bp[jc * 20 + t];

        #pragma unroll
        for (int jc = 0; jc < 5; jc++) {
            #pragma unroll 4
            for (int i = 0; i < HID; i++) {
                float ai = A[i * TPB + tid];
                const float* wr = &Wp[i * HID + jc * 20];
                #pragma unroll
                for (int t = 0; t < 20; t++)
                    acc[jc * 20 + t] = fmaf(wr[t], ai, acc[jc * 20 + t]);
            }
        }
        #pragma unroll
        for (int jc = 0; jc < 5; jc++)
            #pragma unroll
            for (int t = 0; t < 20; t++)
                A[(jc * 20 + t) * TPB + tid] = fmaxf(acc[jc * 20 + t], 0.f);
        Wp = W2t;
        bp = b2;
    }

    // layer 3: HID -> 1
    float out = ib3[k];
    #pragma unroll 4
    for (int i = 0; i < HID; i++)
        out = fmaf(w3[i], A[i * TPB + tid], out);

    // elu(out) + 1  ==  out+1 (out>0)  |  exp(out) (out<=0)
    float dz = (out > 0.f) ? (out + 1.f) : expf(out);

    if (active)
        dzbase[(size_t)k * ROWSK + row] = dz * g_ccw[j];
}

// ---------------- reduction: warp per sample, deterministic shuffle tree -----
__global__ void reduce_kernel(const float* __restrict__ dzk,
                              const float* __restrict__ xin,
                              int k,
                              float* __restrict__ dst)
{
    int n = blockIdx.x * (blockDim.x >> 5) + (threadIdx.x >> 5);
    int lane = threadIdx.x & 31;
    if (n >= NS) return;

    const float* p = dzk + (size_t)n * NQ;
    float s = 0.f;
    for (int j = lane; j < NQ; j += 32) s += p[j];
    #pragma unroll
    for (int o = 16; o; o >>= 1) s += __shfl_xor_sync(0xffffffffu, s, o);

    if (lane == 0) {
        float z = s * xin[n] * 0.5f;
        dst[n] = expf(g_oh[k][1]) * z + g_oh[k][0];
    }
}

// ---------------- launch -----------------------------------------------------
extern "C" void kernel_launch(void* const* d_in, const int* in_sizes, int n_in,
                              void* d_out, int out_size)
{
    const float* logits = (const float*)d_in[0];
    // d_in[1] = nn_id (unused by the reference)
    const float* iW0 = (const float*)d_in[2];
    const float* ib0 = (const float*)d_in[3];
    const float* iW1 = (const float*)d_in[4];
    const float* ib1 = (const float*)d_in[5];
    const float* iW2 = (const float*)d_in[6];
    const float* ib2 = (const float*)d_in[7];
    const float* iW3 = (const float*)d_in[8];
    const float* ib3 = (const float*)d_in[9];
    const float* hW0 = (const float*)d_in[10]; (void)hW0;
    const float* hb0 = (const float*)d_in[11];
    const float* hW1 = (const float*)d_in[12];
    const float* hb1 = (const float*)d_in[13];
    const float* hW2 = (const float*)d_in[14];
    const float* hb2 = (const float*)d_in[15];
    const float* hW3 = (const float*)d_in[16];
    const float* hb3 = (const float*)d_in[17];

    float* out = (float*)d_out;

    void *dz_addr = nullptr, *x2_addr = nullptr;
    cudaGetSymbolAddress(&dz_addr, g_dz);
    cudaGetSymbolAddress(&x2_addr, g_x2);
    float* dz = (float*)dz_addr;
    float* x2 = (float*)x2_addr;

    const int smem_bytes = (HID * TPB + 2 * HID * HID + 6 * HID) * (int)sizeof(float);
    static int attr_done = 0;  // idempotent attribute set (not a work guard)
    cudaFuncSetAttribute(mlp_kernel, cudaFuncAttributeMaxDynamicSharedMemorySize, smem_bytes);
    (void)attr_done;

    // 1) constants
    setup_kernel<<<1, 128>>>(hb0, hW1, hb1, hW2, hb2, hW3, hb3);

    // 2) networks 0 and 1 on x1 = logits
    const int nblk = (ROWSK + TPB - 1) / TPB;
    dim3 g1(nblk, 2);
    mlp_kernel<<<g1, TPB, smem_bytes>>>(logits, 0,
                                        iW0, ib0, iW1, ib1, iW2, ib2, iW3, ib3, dz);

    // 3) reduce k=0 -> x2 ; k=1 -> y1
    const int RWARPS = 8;
    dim3 gr((NS + RWARPS - 1) / RWARPS);
    reduce_kernel<<<gr, RWARPS * 32>>>(dz + 0 * (size_t)ROWSK, logits, 0, x2);
    reduce_kernel<<<gr, RWARPS * 32>>>(dz + 1 * (size_t)ROWSK, logits, 1, out);

    // 4) network 2 on x2
    dim3 g2(nblk, 1);
    mlp_kernel<<<g2, TPB, smem_bytes>>>(x2, 2,
                                        iW0, ib0, iW1, ib1, iW2, ib2, iW3, ib3, dz);

    // 5) reduce k=2 -> y2
    reduce_kernel<<<gr, RWARPS * 32>>>(dz + 2 * (size_t)ROWSK, x2, 2, out + NS);

    // 6) pass-through logits
    cudaMemcpyAsync(out + 2 * NS, logits, NS * sizeof(float), cudaMemcpyDeviceToDevice);
}

// round 4
// speedup vs baseline: 1.1194x; 1.1194x over previous
#include <cuda_runtime.h>
#include <math.h>

#define NS 16384          // samples
#define NB 100            // quadrature order
#define NQ 101            // quadrature points
#define HID 100           // hidden dim
#define ROWSK (NS * NQ)   // rows per network
#define TPB 320           // threads per block in mlp kernel

typedef unsigned long long u64;

// ---- packed f32x2 helpers (FFMA2 only reachable via PTX) --------------------
__device__ __forceinline__ u64 ffma2(u64 a, u64 b, u64 c) {
    u64 d;
    asm("fma.rn.f32x2 %0, %1, %2, %3;" : "=l"(d) : "l"(a), "l"(b), "l"(c));
    return d;
}
__device__ __forceinline__ u64 pack2(float lo, float hi) {
    u64 d;
    asm("mov.b64 %0, {%1, %2};" : "=l"(d) : "f"(lo), "f"(hi));
    return d;
}
__device__ __forceinline__ void unpack2(u64 v, float& lo, float& hi) {
    asm("mov.b64 {%0, %1}, %2;" : "=f"(lo), "=f"(hi) : "l"(v));
}

// ---------------- device globals (scratch; no allocations allowed) ----------
__device__ float g_ccw[NQ];        // Clenshaw-Curtis weights
__device__ float g_csc[NQ];        // (cos(j*pi/NB)+1)/2
__device__ float g_oh[3][2];       // h-MLP(0) outputs per network
__device__ float g_dz[3][ROWSK];   // per-row dz * ccw
__device__ float g_x2[NS];         // mono(0, x1) output

// ---------------- setup: CC quadrature (fp64, matches numpy) + oh constants --
__global__ void setup_kernel(const float* __restrict__ hb0,
                             const float* __restrict__ hW1,
                             const float* __restrict__ hb1,
                             const float* __restrict__ hW2,
                             const float* __restrict__ hb2,
                             const float* __restrict__ hW3,
                             const float* __restrict__ hb3)
{
    const double PI = 3.14159265358979323846;
    int t = threadIdx.x;

    if (t < NQ) {
        double acc = 0.0;
        for (int i = 0; i <= NB; i++) {
            double lij = cos((double)i * (double)t * PI / (double)NB);
            if (t == 0)  lij = 0.5;          // lam[:,0] = 0.5
            if (t == NB) lij *= 0.5;         // lam[:,-1] *= 0.5
            double Wi;
            if (i == 0)      Wi = 1.0;
            else if (i & 1)  Wi = 0.0;
            else             Wi = 2.0 / (1.0 - (double)i * (double)i);
            acc += lij * Wi;
        }
        g_ccw[t] = (float)(acc * 2.0 / (double)NB);
        g_csc[t] = (float)((cos((double)t * PI / (double)NB) + 1.0) * 0.5);
    }

    // oh_k = MLP_h(0): first hidden = relu(bias0)
    __shared__ float hA[HID], hB[HID];
    for (int k = 0; k < 3; k++) {
        if (t < HID) hA[t] = fmaxf(hb0[k * HID + t], 0.f);
        __syncthreads();
        if (t < HID) {
            float s = hb1[k * HID + t];
            for (int i = 0; i < HID; i++) s += hW1[(k * HID + t) * HID + i] * hA[i];
            hB[t] = fmaxf(s, 0.f);
        }
        __syncthreads();
        if (t < HID) {
            float s = hb2[k * HID + t];
            for (int i = 0; i < HID; i++) s += hW2[(k * HID + t) * HID + i] * hB[i];
            hA[t] = fmaxf(s, 0.f);
        }
        __syncthreads();
        if (t < 2) {
            float s = hb3[k * 2 + t];
            for (int i = 0; i < HID; i++) s += hW3[(k * 2 + t) * HID + i] * hA[i];
            g_oh[k][t] = s;
        }
        __syncthreads();
    }
}

// ---------------- main MLP kernel: one thread = one (n,k,j) row --------------
// shared: A[HID][TPB] activations, W1t/W2t transposed weights, small vectors
__global__ __launch_bounds__(TPB, 1)
void mlp_kernel(const float* __restrict__ xin, int kbase,
                const float* __restrict__ iW0, const float* __restrict__ ib0,
                const float* __restrict__ iW1, const float* __restrict__ ib1,
                const float* __restrict__ iW2, const float* __restrict__ ib2,
                const float* __restrict__ iW3, const float* __restrict__ ib3,
                float* __restrict__ dzbase)
{
    extern __shared__ float smem[];
    float* A   = smem;                      // HID*TPB              (8B/16B aligned)
    float* W1t = A   + HID * TPB;           // HID*HID, 16B aligned (W1t[i*HID+j] = W1[j][i])
    float* W2t = W1t + HID * HID;           // 16B aligned
    float* w0  = W2t + HID * HID;           // HID
    float* b0  = w0 + HID;
    float* b1  = b0 + HID;                  // 8B aligned
    float* b2  = b1 + HID;                  // 8B aligned
    float* w3  = b2 + HID;                  // HID

    const int tid = threadIdx.x;
    const int k   = kbase + blockIdx.y;

    // stage (transposed) weights
    for (int idx = tid; idx < HID * HID; idx += TPB) {
        int j = idx / HID, i = idx % HID;
        W1t[i * HID + j] = iW1[(k * HID + j) * HID + i];
        W2t[i * HID + j] = iW2[(k * HID + j) * HID + i];
    }
    for (int idx = tid; idx < HID; idx += TPB) {
        w0[idx] = iW0[(k * HID + idx) * 3];   // only input column 0 matters (h == 0)
        b0[idx] = ib0[k * HID + idx];
        b1[idx] = ib1[k * HID + idx];
        b2[idx] = ib2[k * HID + idx];
        w3[idx] = iW3[k * HID + idx];
    }
    __syncthreads();

    int row = blockIdx.x * TPB + tid;
    bool active = row < ROWSK;
    int n = active ? row / NQ : 0;
    int j = active ? row % NQ : 0;

    float x = xin[n];
    float s = x * g_csc[j];

    // layer 0: scalar -> HID
    #pragma unroll 4
    for (int i = 0; i < HID; i++)
        A[i * TPB + tid] = fmaxf(fmaf(w0[i], s, b0[i]), 0.f);

    // layers 1 and 2: HID -> HID via packed FFMA2.
    // accumulators = 50 x f32x2 (channel pairs); weights read as LDS.128
    // channel-pair vectors; activation replicated once per input channel.
    const float* Wp = W1t;
    const float* bp = b1;
    for (int L = 0; L < 2; L++) {
        u64 acc[HID / 2];
        const u64* bp2 = (const u64*)bp;
        #pragma unroll
        for (int t = 0; t < HID / 2; t++) acc[t] = bp2[t];

        #pragma unroll 2
        for (int i = 0; i < HID; i++) {
            float ai = A[i * TPB + tid];
            u64 a2 = pack2(ai, ai);
            const ulonglong2* wr = (const ulonglong2*)&Wp[i * HID];
            #pragma unroll
            for (int t = 0; t < HID / 4; t++) {
                ulonglong2 w = wr[t];
                acc[2 * t]     = ffma2(a2, w.x, acc[2 * t]);
                acc[2 * t + 1] = ffma2(a2, w.y, acc[2 * t + 1]);
            }
        }

        #pragma unroll
        for (int t = 0; t < HID / 2; t++) {
            float lo, hi;
            unpack2(acc[t], lo, hi);
            A[(2 * t) * TPB + tid]     = fmaxf(lo, 0.f);
            A[(2 * t + 1) * TPB + tid] = fmaxf(hi, 0.f);
        }
        Wp = W2t;
        bp = b2;
    }

    // layer 3: HID -> 1
    float out = ib3[k];
    #pragma unroll 4
    for (int i = 0; i < HID; i++)
        out = fmaf(w3[i], A[i * TPB + tid], out);

    // elu(out) + 1  ==  out+1 (out>0)  |  exp(out) (out<=0)
    float dz = (out > 0.f) ? (out + 1.f) : expf(out);

    if (active)
        dzbase[(size_t)k * ROWSK + row] = dz * g_ccw[j];
}

// ---------------- reduction: warp per sample, deterministic shuffle tree -----
__global__ void reduce_kernel(const float* __restrict__ dzk,
                              const float* __restrict__ xin,
                              int k,
                              float* __restrict__ dst)
{
    int n = blockIdx.x * (blockDim.x >> 5) + (threadIdx.x >> 5);
    int lane = threadIdx.x & 31;
    if (n >= NS) return;

    const float* p = dzk + (size_t)n * NQ;
    float s = 0.f;
    for (int j = lane; j < NQ; j += 32) s += p[j];
    #pragma unroll
    for (int o = 16; o; o >>= 1) s += __shfl_xor_sync(0xffffffffu, s, o);

    if (lane == 0) {
        float z = s * xin[n] * 0.5f;
        dst[n] = expf(g_oh[k][1]) * z + g_oh[k][0];
    }
}

// ---------------- launch -----------------------------------------------------
extern "C" void kernel_launch(void* const* d_in, const int* in_sizes, int n_in,
                              void* d_out, int out_size)
{
    const float* logits = (const float*)d_in[0];
    // d_in[1] = nn_id (unused by the reference)
    const float* iW0 = (const float*)d_in[2];
    const float* ib0 = (const float*)d_in[3];
    const float* iW1 = (const float*)d_in[4];
    const float* ib1 = (const float*)d_in[5];
    const float* iW2 = (const float*)d_in[6];
    const float* ib2 = (const float*)d_in[7];
    const float* iW3 = (const float*)d_in[8];
    const float* ib3 = (const float*)d_in[9];
    const float* hW0 = (const float*)d_in[10]; (void)hW0;
    const float* hb0 = (const float*)d_in[11];
    const float* hW1 = (const float*)d_in[12];
    const float* hb1 = (const float*)d_in[13];
    const float* hW2 = (const float*)d_in[14];
    const float* hb2 = (const float*)d_in[15];
    const float* hW3 = (const float*)d_in[16];
    const float* hb3 = (const float*)d_in[17];

    float* out = (float*)d_out;

    void *dz_addr = nullptr, *x2_addr = nullptr;
    cudaGetSymbolAddress(&dz_addr, g_dz);
    cudaGetSymbolAddress(&x2_addr, g_x2);
    float* dz = (float*)dz_addr;
    float* x2 = (float*)x2_addr;

    const int smem_bytes = (HID * TPB + 2 * HID * HID + 6 * HID) * (int)sizeof(float);
    cudaFuncSetAttribute(mlp_kernel, cudaFuncAttributeMaxDynamicSharedMemorySize, smem_bytes);

    // 1) constants
    setup_kernel<<<1, 128>>>(hb0, hW1, hb1, hW2, hb2, hW3, hb3);

    // 2) networks 0 and 1 on x1 = logits
    const int nblk = (ROWSK + TPB - 1) / TPB;
    dim3 g1(nblk, 2);
    mlp_kernel<<<g1, TPB, smem_bytes>>>(logits, 0,
                                        iW0, ib0, iW1, ib1, iW2, ib2, iW3, ib3, dz);

    // 3) reduce k=0 -> x2 ; k=1 -> y1
    const int RWARPS = 8;
    dim3 gr((NS + RWARPS - 1) / RWARPS);
    reduce_kernel<<<gr, RWARPS * 32>>>(dz + 0 * (size_t)ROWSK, logits, 0, x2);
    reduce_kernel<<<gr, RWARPS * 32>>>(dz + 1 * (size_t)ROWSK, logits, 1, out);

    // 4) network 2 on x2
    dim3 g2(nblk, 1);
    mlp_kernel<<<g2, TPB, smem_bytes>>>(x2, 2,
                                        iW0, ib0, iW1, ib1, iW2, ib2, iW3, ib3, dz);

    // 5) reduce k=2 -> y2
    reduce_kernel<<<gr, RWARPS * 32>>>(dz + 2 * (size_t)ROWSK, x2, 2, out + NS);

    // 6) pass-through logits
    cudaMemcpyAsync(out + 2 * NS, logits, NS * sizeof(float), cudaMemcpyDeviceToDevice);
}

// round 6
// speedup vs baseline: 2.7079x; 2.4191x over previous
#include <cuda_runtime.h>
#include <cuda_bf16.h>
#include <math.h>
#include <stdint.h>

#define NS 16384
#define NB 100
#define NQ 101
#define HID 100
#define ROWSK (NS * NQ)        // 1654784
#define TILEM 128
#define NTILES (ROWSK / TILEM) // 12928 exactly
#define KP 112                 // padded K (7 chunks of 16)
#define NKC 7
#define PITCH 240              // bytes per smem row (112*2 + 16 pad) -> LDSM conflict-free
#define MLP_T 256

typedef unsigned int u32;

// ---- smem layout (byte offsets) ---------------------------------------------
#define AB (TILEM * PITCH)         // 30720 (one A/W tile buffer, 128 rows)
#define OFF_AHI  0
#define OFF_ALO  (AB)
#define OFF_W1HI (2 * AB)
#define OFF_W1LO (3 * AB)
#define OFF_W2HI (4 * AB)
#define OFF_W2LO (5 * AB)
#define OFF_RED  (6 * AB)          // 128 rows * 4 warpgroups * 4B = 2048
#define OFF_VEC  (OFF_RED + 2048)  // b1[128] b2[128] w3[128] w0[128] b0[128]
#define SMEM_ALLOC (OFF_VEC + 5 * 128 * 4 + 256)

// ---------------- device globals (scratch) -----------------------------------
__device__ float g_ccw[NQ];
__device__ float g_csc[NQ];
__device__ float g_oh[3][2];
__device__ float g_dz[3][ROWSK];
__device__ float g_x2[NS];

// ---------------- PTX helpers (base-ISA only: ldmatrix + mma.sync) -----------
__device__ __forceinline__ u32 smem_u32(const void* p) {
    u32 a;
    asm("{ .reg .u64 t; cvta.to.shared.u64 t, %1; cvt.u32.u64 %0, t; }" : "=r"(a) : "l"(p));
    return a;
}
__device__ __forceinline__ void ldsm4(u32* r, u32 a) {
    asm volatile("ldmatrix.sync.aligned.m8n8.x4.shared.b16 {%0,%1,%2,%3}, [%4];"
                 : "=r"(r[0]), "=r"(r[1]), "=r"(r[2]), "=r"(r[3]) : "r"(a));
}
__device__ __forceinline__ void ldsm2(u32* r, u32 a) {
    asm volatile("ldmatrix.sync.aligned.m8n8.x2.shared.b16 {%0,%1}, [%2];"
                 : "=r"(r[0]), "=r"(r[1]) : "r"(a));
}
__device__ __forceinline__ void mma16816(float* c, const u32* a, const u32* b) {
    asm volatile("mma.sync.aligned.m16n8k16.row.col.f32.bf16.bf16.f32 "
                 "{%0,%1,%2,%3}, {%4,%5,%6,%7}, {%8,%9}, {%0,%1,%2,%3};"
                 : "+f"(c[0]), "+f"(c[1]), "+f"(c[2]), "+f"(c[3])
                 : "r"(a[0]), "r"(a[1]), "r"(a[2]), "r"(a[3]), "r"(b[0]), "r"(b[1]));
}

__device__ __forceinline__ unsigned short bf_bits(float f) {
    __nv_bfloat16 b = __float2bfloat16(f);
    return *reinterpret_cast<unsigned short*>(&b);
}
__device__ __forceinline__ float bf_val(float f) {
    return __bfloat162float(__float2bfloat16(f));
}
__device__ __forceinline__ u32 pack_hi(float f0, float f1) {
    return (u32)bf_bits(f0) | ((u32)bf_bits(f1) << 16);
}
__device__ __forceinline__ u32 pack_lo(float f0, float f1) {
    return (u32)bf_bits(f0 - bf_val(f0)) | ((u32)bf_bits(f1 - bf_val(f1)) << 16);
}

// ---------------- setup: CC quadrature (fp64) + oh constants -----------------
__global__ void setup_kernel(const float* __restrict__ hb0,
                             const float* __restrict__ hW1,
                             const float* __restrict__ hb1,
                             const float* __restrict__ hW2,
                             const float* __restrict__ hb2,
                             const float* __restrict__ hW3,
                             const float* __restrict__ hb3)
{
    const double PI = 3.14159265358979323846;
    int t = threadIdx.x;
    if (t < NQ) {
        double acc = 0.0;
        for (int i = 0; i <= NB; i++) {
            double lij = cos((double)i * (double)t * PI / (double)NB);
            if (t == 0)  lij = 0.5;
            if (t == NB) lij *= 0.5;
            double Wi;
            if (i == 0)      Wi = 1.0;
            else if (i & 1)  Wi = 0.0;
            else             Wi = 2.0 / (1.0 - (double)i * (double)i);
            acc += lij * Wi;
        }
        g_ccw[t] = (float)(acc * 2.0 / (double)NB);
        g_csc[t] = (float)((cos((double)t * PI / (double)NB) + 1.0) * 0.5);
    }
    __shared__ float hA[HID], hB[HID];
    for (int k = 0; k < 3; k++) {
        if (t < HID) hA[t] = fmaxf(hb0[k * HID + t], 0.f);
        __syncthreads();
        if (t < HID) {
            float s = hb1[k * HID + t];
            for (int i = 0; i < HID; i++) s += hW1[(k * HID + t) * HID + i] * hA[i];
            hB[t] = fmaxf(s, 0.f);
        }
        __syncthreads();
        if (t < HID) {
            float s = hb2[k * HID + t];
            for (int i = 0; i < HID; i++) s += hW2[(k * HID + t) * HID + i] * hB[i];
            hA[t] = fmaxf(s, 0.f);
        }
        __syncthreads();
        if (t < 2) {
            float s = hb3[k * 2 + t];
            for (int i = 0; i < HID; i++) s += hW3[(k * 2 + t) * HID + i] * hA[i];
            g_oh[k][t] = s;
        }
        __syncthreads();
    }
}

// ---------------- tensor-core MLP kernel (mma.sync, persistent CTAs) ---------
// Warp grid: 2 (M-groups of 4 m16-tiles) x 4 (N-groups of 4 n8-tiles).
// Split-bf16: acc = Ahi*Whi + Ahi*Wlo + Alo*Whi  (fp32 accumulate).
__global__ __launch_bounds__(MLP_T, 1)
void mlp_tc(const float* __restrict__ xin, int kbase,
            const float* __restrict__ iW0, const float* __restrict__ ib0,
            const float* __restrict__ iW1, const float* __restrict__ ib1,
            const float* __restrict__ iW2, const float* __restrict__ ib2,
            const float* __restrict__ iW3, const float* __restrict__ ib3,
            float* __restrict__ dzbase)
{
    extern __shared__ char ab[];
    const u32 sm = smem_u32(ab);

    const int tid  = threadIdx.x;
    const int lane = tid & 31;
    const int wid  = tid >> 5;
    const int wm   = wid >> 2;   // 0..1  (M group)
    const int wn   = wid & 3;    // 0..3  (N group)
    const int k    = kbase + blockIdx.y;

    // zero A + W buffers (establishes K/N pads)
    for (int i = tid; i < (6 * AB) / 16; i += MLP_T)
        reinterpret_cast<uint4*>(ab)[i] = make_uint4(0, 0, 0, 0);

    float* redv = (float*)(ab + OFF_RED);
    float* b1v  = (float*)(ab + OFF_VEC);
    float* b2v  = b1v + 128;
    float* w3v  = b2v + 128;
    float* w0v  = w3v + 128;
    float* b0v  = w0v + 128;
    __syncthreads();

    for (int i = tid; i < 128; i += MLP_T) {
        b1v[i] = (i < HID) ? ib1[k * HID + i] : 0.f;
        b2v[i] = (i < HID) ? ib2[k * HID + i] : 0.f;
        w3v[i] = (i < HID) ? iW3[k * HID + i] : 0.f;
        w0v[i] = (i < HID) ? iW0[(k * HID + i) * 3] : 0.f;  // h==0: input col 0 only
        b0v[i] = (i < HID) ? ib0[k * HID + i] : 0.f;
    }
    // stage W1/W2 hi/lo as [N][K] bf16, pitch 240B
    for (int idx = tid; idx < HID * HID; idx += MLP_T) {
        int o = idx / HID, i = idx % HID;
        float w1 = iW1[(k * HID + o) * HID + i];
        float w2 = iW2[(k * HID + o) * HID + i];
        u32 off = o * PITCH + i * 2;
        *(unsigned short*)(ab + OFF_W1HI + off) = bf_bits(w1);
        *(unsigned short*)(ab + OFF_W1LO + off) = bf_bits(w1 - bf_val(w1));
        *(unsigned short*)(ab + OFF_W2HI + off) = bf_bits(w2);
        *(unsigned short*)(ab + OFF_W2LO + off) = bf_bits(w2 - bf_val(w2));
    }
    __syncthreads();

    // lane-dependent ldmatrix address terms
    const u32 a_l = (u32)((lane & 15) * PITCH + ((lane >> 4) & 1) * 16);
    const u32 b_l = (u32)((lane & 7) * PITCH + ((lane >> 3) & 1) * 16);
    const u32 sAhi = sm + OFF_AHI, sAlo = sm + OFF_ALO;

    const float b3 = ib3[k];

    for (int tile = blockIdx.x; tile < NTILES; tile += gridDim.x) {
        // ---- layer 0: scalar -> 100, split to bf16 hi/lo in A ----
        {
            int r0 = tid >> 1;
            int row = tile * TILEM + r0;
            int n = row / NQ, j = row - n * NQ;
            float sv = xin[n] * g_csc[j];
            int cbase = (tid & 1) * 50;
            char* ahi = ab + OFF_AHI + r0 * PITCH;
            char* alo = ab + OFF_ALO + r0 * PITCH;
            #pragma unroll
            for (int p = 0; p < 25; p++) {
                int c = cbase + 2 * p;
                float v0 = fmaxf(fmaf(w0v[c], sv, b0v[c]), 0.f);
                float v1 = fmaxf(fmaf(w0v[c + 1], sv, b0v[c + 1]), 0.f);
                *(u32*)(ahi + c * 2) = pack_hi(v0, v1);
                *(u32*)(alo + c * 2) = pack_lo(v0, v1);
            }
        }
        __syncthreads();

        // ---- layers 1 & 2 via mma.sync ----
        for (int L = 0; L < 2; L++) {
            const u32 sWhi = sm + (L ? OFF_W2HI : OFF_W1HI);
            const u32 sWlo = sm + (L ? OFF_W2LO : OFF_W1LO);

            float acc[4][4][4];
            #pragma unroll
            for (int mi = 0; mi < 4; mi++)
                #pragma unroll
                for (int ni = 0; ni < 4; ni++)
                    #pragma unroll
                    for (int e = 0; e < 4; e++) acc[mi][ni][e] = 0.f;

            for (int kc = 0; kc < NKC; kc++) {
                u32 ah[4][4], al[4][4], bh[4][2], bl[4][2];
                #pragma unroll
                for (int mi = 0; mi < 4; mi++) {
                    u32 aoff = (u32)((wm * 4 + mi) * (16 * PITCH) + kc * 32) + a_l;
                    ldsm4(ah[mi], sAhi + aoff);
                    ldsm4(al[mi], sAlo + aoff);
                }
                #pragma unroll
                for (int ni = 0; ni < 4; ni++) {
                    u32 boff = (u32)((wn * 4 + ni) * (8 * PITCH) + kc * 32) + b_l;
                    ldsm2(bh[ni], sWhi + boff);
                    ldsm2(bl[ni], sWlo + boff);
                }
                #pragma unroll
                for (int mi = 0; mi < 4; mi++)
                    #pragma unroll
                    for (int ni = 0; ni < 4; ni++) {
                        mma16816(acc[mi][ni], ah[mi], bh[ni]);
                        mma16816(acc[mi][ni], ah[mi], bl[ni]);
                        mma16816(acc[mi][ni], al[mi], bh[ni]);
                    }
            }
            __syncthreads();   // all A reads complete before overwrite

            if (L == 0) {
                // epilogue: bias + relu, split, write back to A
                #pragma unroll
                for (int mi = 0; mi < 4; mi++) {
                    int r0 = (wm * 4 + mi) * 16 + (lane >> 2);
                    #pragma unroll
                    for (int ni = 0; ni < 4; ni++) {
                        int c0 = (wn * 4 + ni) * 8 + (lane & 3) * 2;
                        if (c0 < HID) {
                            float bb0 = b1v[c0], bb1 = b1v[c0 + 1];
                            float v0 = fmaxf(acc[mi][ni][0] + bb0, 0.f);
                            float v1 = fmaxf(acc[mi][ni][1] + bb1, 0.f);
                            float v2 = fmaxf(acc[mi][ni][2] + bb0, 0.f);
                            float v3 = fmaxf(acc[mi][ni][3] + bb1, 0.f);
                            u32 o0 = r0 * PITCH + c0 * 2;
                            u32 o1 = (r0 + 8) * PITCH + c0 * 2;
                            *(u32*)(ab + OFF_AHI + o0) = pack_hi(v0, v1);
                            *(u32*)(ab + OFF_ALO + o0) = pack_lo(v0, v1);
                            *(u32*)(ab + OFF_AHI + o1) = pack_hi(v2, v3);
                            *(u32*)(ab + OFF_ALO + o1) = pack_lo(v2, v3);
                        }
                    }
                }
                __syncthreads();
            } else {
                // layer 3: weighted partial dot per thread, warp shfl, smem reduce
                float rp[4][2];
                #pragma unroll
                for (int mi = 0; mi < 4; mi++) { rp[mi][0] = 0.f; rp[mi][1] = 0.f; }
                #pragma unroll
                for (int ni = 0; ni < 4; ni++) {
                    int c0 = (wn * 4 + ni) * 8 + (lane & 3) * 2;
                    if (c0 < HID) {
                        float bb0 = b2v[c0], bb1 = b2v[c0 + 1];
                        float w30 = w3v[c0], w31 = w3v[c0 + 1];
                        #pragma unroll
                        for (int mi = 0; mi < 4; mi++) {
                            float v0 = fmaxf(acc[mi][ni][0] + bb0, 0.f);
                            float v1 = fmaxf(acc[mi][ni][1] + bb1, 0.f);
                            float v2 = fmaxf(acc[mi][ni][2] + bb0, 0.f);
                            float v3 = fmaxf(acc[mi][ni][3] + bb1, 0.f);
                            rp[mi][0] = fmaf(w30, v0, fmaf(w31, v1, rp[mi][0]));
                            rp[mi][1] = fmaf(w30, v2, fmaf(w31, v3, rp[mi][1]));
                        }
                    }
                }
                #pragma unroll
                for (int mi = 0; mi < 4; mi++) {
                    #pragma unroll
                    for (int e = 0; e < 2; e++) {
                        rp[mi][e] += __shfl_xor_sync(0xffffffffu, rp[mi][e], 1);
                        rp[mi][e] += __shfl_xor_sync(0xffffffffu, rp[mi][e], 2);
                    }
                }
                if ((lane & 3) == 0) {
                    #pragma unroll
                    for (int mi = 0; mi < 4; mi++) {
                        int r0 = (wm * 4 + mi) * 16 + (lane >> 2);
                        redv[r0 * 4 + wn] = rp[mi][0];
                        redv[(r0 + 8) * 4 + wn] = rp[mi][1];
                    }
                }
                __syncthreads();
                if (tid < TILEM) {
                    int row = tile * TILEM + tid;
                    int j = row % NQ;
                    float out = redv[tid * 4] + redv[tid * 4 + 1]
                              + redv[tid * 4 + 2] + redv[tid * 4 + 3] + b3;
                    float dz = (out > 0.f) ? (out + 1.f) : expf(out);
                    dzbase[(size_t)k * ROWSK + row] = dz * g_ccw[j];
                }
            }
        }
    }
}

// ---------------- reduction: warp per sample ---------------------------------
__global__ void reduce_kernel(const float* __restrict__ dzk,
                              const float* __restrict__ xin,
                              int k,
                              float* __restrict__ dst)
{
    int n = blockIdx.x * (blockDim.x >> 5) + (threadIdx.x >> 5);
    int lane = threadIdx.x & 31;
    if (n >= NS) return;
    const float* p = dzk + (size_t)n * NQ;
    float s = 0.f;
    for (int j = lane; j < NQ; j += 32) s += p[j];
    #pragma unroll
    for (int o = 16; o; o >>= 1) s += __shfl_xor_sync(0xffffffffu, s, o);
    if (lane == 0) {
        float z = s * xin[n] * 0.5f;
        dst[n] = expf(g_oh[k][1]) * z + g_oh[k][0];
    }
}

// ---------------- launch -----------------------------------------------------
extern "C" void kernel_launch(void* const* d_in, const int* in_sizes, int n_in,
                              void* d_out, int out_size)
{
    const float* logits = (const float*)d_in[0];
    const float* iW0 = (const float*)d_in[2];
    const float* ib0 = (const float*)d_in[3];
    const float* iW1 = (const float*)d_in[4];
    const float* ib1 = (const float*)d_in[5];
    const float* iW2 = (const float*)d_in[6];
    const float* ib2 = (const float*)d_in[7];
    const float* iW3 = (const float*)d_in[8];
    const float* ib3 = (const float*)d_in[9];
    const float* hb0 = (const float*)d_in[11];
    const float* hW1 = (const float*)d_in[12];
    const float* hb1 = (const float*)d_in[13];
    const float* hW2 = (const float*)d_in[14];
    const float* hb2 = (const float*)d_in[15];
    const float* hW3 = (const float*)d_in[16];
    const float* hb3 = (const float*)d_in[17];

    float* out = (float*)d_out;

    void *dz_addr = nullptr, *x2_addr = nullptr;
    cudaGetSymbolAddress(&dz_addr, g_dz);
    cudaGetSymbolAddress(&x2_addr, g_x2);
    float* dz = (float*)dz_addr;
    float* x2 = (float*)x2_addr;

    cudaFuncSetAttribute(mlp_tc, cudaFuncAttributeMaxDynamicSharedMemorySize, SMEM_ALLOC);

    // 1) constants
    setup_kernel<<<1, 128>>>(hb0, hW1, hb1, hW2, hb2, hW3, hb3);

    // 2) networks 0 and 1 on x1 = logits
    dim3 g1(148, 2);
    mlp_tc<<<g1, MLP_T, SMEM_ALLOC>>>(logits, 0,
                                      iW0, ib0, iW1, ib1, iW2, ib2, iW3, ib3, dz);

    // 3) reduce k=0 -> x2 ; k=1 -> y1
    const int RWARPS = 8;
    dim3 gr((NS + RWARPS - 1) / RWARPS);
    reduce_kernel<<<gr, RWARPS * 32>>>(dz + 0 * (size_t)ROWSK, logits, 0, x2);
    reduce_kernel<<<gr, RWARPS * 32>>>(dz + 1 * (size_t)ROWSK, logits, 1, out);

    // 4) network 2 on x2
    dim3 g2(148, 1);
    mlp_tc<<<g2, MLP_T, SMEM_ALLOC>>>(x2, 2,
                                      iW0, ib0, iW1, ib1, iW2, ib2, iW3, ib3, dz);

    // 5) reduce k=2 -> y2
    reduce_kernel<<<gr, RWARPS * 32>>>(dz + 2 * (size_t)ROWSK, x2, 2, out + NS);

    // 6) pass-through logits
    cudaMemcpyAsync(out + 2 * NS, logits, NS * sizeof(float), cudaMemcpyDeviceToDevice);
}

// round 7
// speedup vs baseline: 3.0326x; 1.1199x over previous
#include <cuda_runtime.h>
#include <cuda_fp16.h>
#include <math.h>
#include <stdint.h>

#define NS 16384
#define NB 100
#define NQ 101
#define HID 100
#define ROWSK (NS * NQ)        // 1654784
#define TILEM 128
#define NTILES (ROWSK / TILEM) // 12928 exactly
#define KP 112                 // padded K (7 chunks of 16)
#define NKC 7
#define PITCH 240              // bytes per smem row (112*2 + 16 pad) -> LDSM conflict-free
#define MLP_T 256

typedef unsigned int u32;

// ---- smem layout (byte offsets) ---------------------------------------------
#define AB (TILEM * PITCH)         // 30720
#define OFF_AHI  0
#define OFF_ALO  (AB)
#define OFF_W1   (2 * AB)          // W hi only (fp16 2-product scheme)
#define OFF_W2   (3 * AB)
#define OFF_RED  (4 * AB)
#define OFF_VEC  (OFF_RED + 2048)  // b1[128] b2[128] w3[128] w0[128] b0[128]
#define SMEM_ALLOC (OFF_VEC + 5 * 128 * 4 + 256)

// ---------------- device globals (scratch) -----------------------------------
__device__ float g_ccw[NQ];
__device__ float g_csc[NQ];
__device__ float g_oh[3][2];
__device__ float g_dz[3][ROWSK];
__device__ float g_x2[NS];

// ---------------- PTX helpers (base-ISA only: ldmatrix + mma.sync) -----------
__device__ __forceinline__ u32 smem_u32(const void* p) {
    u32 a;
    asm("{ .reg .u64 t; cvta.to.shared.u64 t, %1; cvt.u32.u64 %0, t; }" : "=r"(a) : "l"(p));
    return a;
}
__device__ __forceinline__ void ldsm4(u32* r, u32 a) {
    asm volatile("ldmatrix.sync.aligned.m8n8.x4.shared.b16 {%0,%1,%2,%3}, [%4];"
                 : "=r"(r[0]), "=r"(r[1]), "=r"(r[2]), "=r"(r[3]) : "r"(a));
}
__device__ __forceinline__ void ldsm2(u32* r, u32 a) {
    asm volatile("ldmatrix.sync.aligned.m8n8.x2.shared.b16 {%0,%1}, [%2];"
                 : "=r"(r[0]), "=r"(r[1]) : "r"(a));
}
__device__ __forceinline__ void mma16816(float* c, const u32* a, const u32* b) {
    asm volatile("mma.sync.aligned.m16n8k16.row.col.f32.f16.f16.f32 "
                 "{%0,%1,%2,%3}, {%4,%5,%6,%7}, {%8,%9}, {%0,%1,%2,%3};"
                 : "+f"(c[0]), "+f"(c[1]), "+f"(c[2]), "+f"(c[3])
                 : "r"(a[0]), "r"(a[1]), "r"(a[2]), "r"(a[3]), "r"(b[0]), "r"(b[1]));
}

__device__ __forceinline__ unsigned short h_bits(float f) {
    __half h = __float2half_rn(f);
    return *reinterpret_cast<unsigned short*>(&h);
}
__device__ __forceinline__ float h_val(float f) {
    return __half2float(__float2half_rn(f));
}
__device__ __forceinline__ u32 pack_hi(float f0, float f1) {
    return (u32)h_bits(f0) | ((u32)h_bits(f1) << 16);
}
__device__ __forceinline__ u32 pack_lo(float f0, float f1) {
    return (u32)h_bits(f0 - h_val(f0)) | ((u32)h_bits(f1 - h_val(f1)) << 16);
}

// ---------------- setup: CC quadrature (fp64) + oh constants -----------------
__global__ void setup_kernel(const float* __restrict__ hb0,
                             const float* __restrict__ hW1,
                             const float* __restrict__ hb1,
                             const float* __restrict__ hW2,
                             const float* __restrict__ hb2,
                             const float* __restrict__ hW3,
                             const float* __restrict__ hb3)
{
    const double PI = 3.14159265358979323846;
    int t = threadIdx.x;
    if (t < NQ) {
        double acc = 0.0;
        for (int i = 0; i <= NB; i++) {
            double lij = cos((double)i * (double)t * PI / (double)NB);
            if (t == 0)  lij = 0.5;
            if (t == NB) lij *= 0.5;
            double Wi;
            if (i == 0)      Wi = 1.0;
            else if (i & 1)  Wi = 0.0;
            else             Wi = 2.0 / (1.0 - (double)i * (double)i);
            acc += lij * Wi;
        }
        g_ccw[t] = (float)(acc * 2.0 / (double)NB);
        g_csc[t] = (float)((cos((double)t * PI / (double)NB) + 1.0) * 0.5);
    }
    __shared__ float hA[HID], hB[HID];
    for (int k = 0; k < 3; k++) {
        if (t < HID) hA[t] = fmaxf(hb0[k * HID + t], 0.f);
        __syncthreads();
        if (t < HID) {
            float s = hb1[k * HID + t];
            for (int i = 0; i < HID; i++) s += hW1[(k * HID + t) * HID + i] * hA[i];
            hB[t] = fmaxf(s, 0.f);
        }
        __syncthreads();
        if (t < HID) {
            float s = hb2[k * HID + t];
            for (int i = 0; i < HID; i++) s += hW2[(k * HID + t) * HID + i] * hB[i];
            hA[t] = fmaxf(s, 0.f);
        }
        __syncthreads();
        if (t < 2) {
            float s = hb3[k * 2 + t];
            for (int i = 0; i < HID; i++) s += hW3[(k * 2 + t) * HID + i] * hA[i];
            g_oh[k][t] = s;
        }
        __syncthreads();
    }
}

// ---------------- tensor-core MLP kernel (mma.sync fp16, persistent CTAs) ----
// Warp grid: 2 (M) x 4 (N).  N = 13 n8-tiles, partitioned 4/3/3/3 per wn.
// Split-fp16: acc = Ahi*W + Alo*W  (A exact to 2^-22, W quantized to 2^-11).
__global__ __launch_bounds__(MLP_T, 1)
void mlp_tc(const float* __restrict__ xin, int kbase,
            const float* __restrict__ iW0, const float* __restrict__ ib0,
            const float* __restrict__ iW1, const float* __restrict__ ib1,
            const float* __restrict__ iW2, const float* __restrict__ ib2,
            const float* __restrict__ iW3, const float* __restrict__ ib3,
            float* __restrict__ dzbase)
{
    extern __shared__ char ab[];
    const u32 sm = smem_u32(ab);

    const int tid  = threadIdx.x;
    const int lane = tid & 31;
    const int wid  = tid >> 5;
    const int wm   = wid >> 2;   // 0..1  (M group)
    const int wn   = wid & 3;    // 0..3  (N group)
    const int k    = kbase + blockIdx.y;

    // N-tile partition: wn0 -> tiles [0,4), wn1 -> [4,7), wn2 -> [7,10), wn3 -> [10,13)
    const int nt0  = (wn == 0) ? 0 : (1 + 3 * wn);
    const int ncnt = (wn == 0) ? 4 : 3;

    // zero A + W buffers (establishes K/N pads)
    for (int i = tid; i < (4 * AB) / 16; i += MLP_T)
        reinterpret_cast<uint4*>(ab)[i] = make_uint4(0, 0, 0, 0);

    float* redv = (float*)(ab + OFF_RED);
    float* b1v  = (float*)(ab + OFF_VEC);
    float* b2v  = b1v + 128;
    float* w3v  = b2v + 128;
    float* w0v  = w3v + 128;
    float* b0v  = w0v + 128;
    __syncthreads();

    for (int i = tid; i < 128; i += MLP_T) {
        b1v[i] = (i < HID) ? ib1[k * HID + i] : 0.f;
        b2v[i] = (i < HID) ? ib2[k * HID + i] : 0.f;
        w3v[i] = (i < HID) ? iW3[k * HID + i] : 0.f;
        w0v[i] = (i < HID) ? iW0[(k * HID + i) * 3] : 0.f;  // h==0: input col 0 only
        b0v[i] = (i < HID) ? ib0[k * HID + i] : 0.f;
    }
    // stage W1/W2 (fp16 hi only) as [N][K], pitch 240B
    for (int idx = tid; idx < HID * HID; idx += MLP_T) {
        int o = idx / HID, i = idx % HID;
        u32 off = o * PITCH + i * 2;
        *(unsigned short*)(ab + OFF_W1 + off) = h_bits(iW1[(k * HID + o) * HID + i]);
        *(unsigned short*)(ab + OFF_W2 + off) = h_bits(iW2[(k * HID + o) * HID + i]);
    }
    __syncthreads();

    // lane-dependent ldmatrix address terms
    const u32 a_l = (u32)((lane & 15) * PITCH + ((lane >> 4) & 1) * 16);
    const u32 b_l = (u32)((lane & 7) * PITCH + ((lane >> 3) & 1) * 16);
    const u32 sAhi = sm + OFF_AHI, sAlo = sm + OFF_ALO;

    const float b3 = ib3[k];

    for (int tile = blockIdx.x; tile < NTILES; tile += gridDim.x) {
        // ---- layer 0: scalar -> 100, split to fp16 hi/lo in A ----
        {
            int r0 = tid >> 1;
            int row = tile * TILEM + r0;
            int n = row / NQ, j = row - n * NQ;
            float sv = xin[n] * g_csc[j];
            int cbase = (tid & 1) * 50;
            char* ahi = ab + OFF_AHI + r0 * PITCH;
            char* alo = ab + OFF_ALO + r0 * PITCH;
            #pragma unroll
            for (int p = 0; p < 25; p++) {
                int c = cbase + 2 * p;
                float v0 = fmaxf(fmaf(w0v[c], sv, b0v[c]), 0.f);
                float v1 = fmaxf(fmaf(w0v[c + 1], sv, b0v[c + 1]), 0.f);
                *(u32*)(ahi + c * 2) = pack_hi(v0, v1);
                *(u32*)(alo + c * 2) = pack_lo(v0, v1);
            }
        }
        __syncthreads();

        // ---- layers 1 & 2 via mma.sync ----
        for (int L = 0; L < 2; L++) {
            const u32 sW = sm + (L ? OFF_W2 : OFF_W1);

            float acc[4][4][4];
            #pragma unroll
            for (int mi = 0; mi < 4; mi++)
                #pragma unroll
                for (int ni = 0; ni < 4; ni++)
                    #pragma unroll
                    for (int e = 0; e < 4; e++) acc[mi][ni][e] = 0.f;

            for (int kc = 0; kc < NKC; kc++) {
                u32 ah[4][4], al[4][4], bh[4][2];
                #pragma unroll
                for (int mi = 0; mi < 4; mi++) {
                    u32 aoff = (u32)((wm * 4 + mi) * (16 * PITCH) + kc * 32) + a_l;
                    ldsm4(ah[mi], sAhi + aoff);
                    ldsm4(al[mi], sAlo + aoff);
                }
                #pragma unroll
                for (int ni = 0; ni < 4; ni++) {
                    if (ni < ncnt) {
                        u32 boff = (u32)((nt0 + ni) * (8 * PITCH) + kc * 32) + b_l;
                        ldsm2(bh[ni], sW + boff);
                    }
                }
                #pragma unroll
                for (int mi = 0; mi < 4; mi++)
                    #pragma unroll
                    for (int ni = 0; ni < 4; ni++) {
                        if (ni < ncnt) {
                            mma16816(acc[mi][ni], ah[mi], bh[ni]);
                            mma16816(acc[mi][ni], al[mi], bh[ni]);
                        }
                    }
            }
            __syncthreads();   // all A reads complete before overwrite

            if (L == 0) {
                // epilogue: bias + relu, split, write back to A
                #pragma unroll
                for (int mi = 0; mi < 4; mi++) {
                    int r0 = (wm * 4 + mi) * 16 + (lane >> 2);
                    #pragma unroll
                    for (int ni = 0; ni < 4; ni++) {
                        int c0 = (nt0 + ni) * 8 + (lane & 3) * 2;
                        if (ni < ncnt && c0 < HID) {
                            float bb0 = b1v[c0], bb1 = b1v[c0 + 1];
                            float v0 = fmaxf(acc[mi][ni][0] + bb0, 0.f);
                            float v1 = fmaxf(acc[mi][ni][1] + bb1, 0.f);
                            float v2 = fmaxf(acc[mi][ni][2] + bb0, 0.f);
                            float v3 = fmaxf(acc[mi][ni][3] + bb1, 0.f);
                            u32 o0 = r0 * PITCH + c0 * 2;
                            u32 o1 = (r0 + 8) * PITCH + c0 * 2;
                            *(u32*)(ab + OFF_AHI + o0) = pack_hi(v0, v1);
                            *(u32*)(ab + OFF_ALO + o0) = pack_lo(v0, v1);
                            *(u32*)(ab + OFF_AHI + o1) = pack_hi(v2, v3);
                            *(u32*)(ab + OFF_ALO + o1) = pack_lo(v2, v3);
                        }
                    }
                }
                __syncthreads();
            } else {
                // layer 3: weighted partial dot per thread, warp shfl, smem reduce
                float rp[4][2];
                #pragma unroll
                for (int mi = 0; mi < 4; mi++) { rp[mi][0] = 0.f; rp[mi][1] = 0.f; }
                #pragma unroll
                for (int ni = 0; ni < 4; ni++) {
                    int c0 = (nt0 + ni) * 8 + (lane & 3) * 2;
                    if (ni < ncnt && c0 < HID) {
                        float bb0 = b2v[c0], bb1 = b2v[c0 + 1];
                        float w30 = w3v[c0], w31 = w3v[c0 + 1];
                        #pragma unroll
                        for (int mi = 0; mi < 4; mi++) {
                            float v0 = fmaxf(acc[mi][ni][0] + bb0, 0.f);
                            float v1 = fmaxf(acc[mi][ni][1] + bb1, 0.f);
                            float v2 = fmaxf(acc[mi][ni][2] + bb0, 0.f);
                            float v3 = fmaxf(acc[mi][ni][3] + bb1, 0.f);
                            rp[mi][0] = fmaf(w30, v0, fmaf(w31, v1, rp[mi][0]));
                            rp[mi][1] = fmaf(w30, v2, fmaf(w31, v3, rp[mi][1]));
                        }
                    }
                }
                #pragma unroll
                for (int mi = 0; mi < 4; mi++) {
                    #pragma unroll
                    for (int e = 0; e < 2; e++) {
                        rp[mi][e] += __shfl_xor_sync(0xffffffffu, rp[mi][e], 1);
                        rp[mi][e] += __shfl_xor_sync(0xffffffffu, rp[mi][e], 2);
                    }
                }
                if ((lane & 3) == 0) {
                    #pragma unroll
                    for (int mi = 0; mi < 4; mi++) {
                        int r0 = (wm * 4 + mi) * 16 + (lane >> 2);
                        redv[r0 * 4 + wn] = rp[mi][0];
                        redv[(r0 + 8) * 4 + wn] = rp[mi][1];
                    }
                }
                __syncthreads();
                if (tid < TILEM) {
                    int row = tile * TILEM + tid;
                    int j = row % NQ;
                    float out = redv[tid * 4] + redv[tid * 4 + 1]
                              + redv[tid * 4 + 2] + redv[tid * 4 + 3] + b3;
                    float dz = (out > 0.f) ? (out + 1.f) : expf(out);
                    dzbase[(size_t)k * ROWSK + row] = dz * g_ccw[j];
                }
            }
        }
    }
}

// ---------------- reduction: warp per sample ---------------------------------
__global__ void reduce_kernel(const float* __restrict__ dzk,
                              const float* __restrict__ xin,
                              int k,
                              float* __restrict__ dst)
{
    int n = blockIdx.x * (blockDim.x >> 5) + (threadIdx.x >> 5);
    int lane = threadIdx.x & 31;
    if (n >= NS) return;
    const float* p = dzk + (size_t)n * NQ;
    float s = 0.f;
    for (int j = lane; j < NQ; j += 32) s += p[j];
    #pragma unroll
    for (int o = 16; o; o >>= 1) s += __shfl_xor_sync(0xffffffffu, s, o);
    if (lane == 0) {
        float z = s * xin[n] * 0.5f;
        dst[n] = expf(g_oh[k][1]) * z + g_oh[k][0];
    }
}

// ---------------- launch -----------------------------------------------------
extern "C" void kernel_launch(void* const* d_in, const int* in_sizes, int n_in,
                              void* d_out, int out_size)
{
    const float* logits = (const float*)d_in[0];
    const float* iW0 = (const float*)d_in[2];
    const float* ib0 = (const float*)d_in[3];
    const float* iW1 = (const float*)d_in[4];
    const float* ib1 = (const float*)d_in[5];
    const float* iW2 = (const float*)d_in[6];
    const float* ib2 = (const float*)d_in[7];
    const float* iW3 = (const float*)d_in[8];
    const float* ib3 = (const float*)d_in[9];
    const float* hb0 = (const float*)d_in[11];
    const float* hW1 = (const float*)d_in[12];
    const float* hb1 = (const float*)d_in[13];
    const float* hW2 = (const float*)d_in[14];
    const float* hb2 = (const float*)d_in[15];
    const float* hW3 = (const float*)d_in[16];
    const float* hb3 = (const float*)d_in[17];

    float* out = (float*)d_out;

    void *dz_addr = nullptr, *x2_addr = nullptr;
    cudaGetSymbolAddress(&dz_addr, g_dz);
    cudaGetSymbolAddress(&x2_addr, g_x2);
    float* dz = (float*)dz_addr;
    float* x2 = (float*)x2_addr;

    cudaFuncSetAttribute(mlp_tc, cudaFuncAttributeMaxDynamicSharedMemorySize, SMEM_ALLOC);

    // 1) constants
    setup_kernel<<<1, 128>>>(hb0, hW1, hb1, hW2, hb2, hW3, hb3);

    // 2) networks 0 and 1 on x1 = logits
    dim3 g1(148, 2);
    mlp_tc<<<g1, MLP_T, SMEM_ALLOC>>>(logits, 0,
                                      iW0, ib0, iW1, ib1, iW2, ib2, iW3, ib3, dz);

    // 3) reduce k=0 -> x2 ; k=1 -> y1
    const int RWARPS = 8;
    dim3 gr((NS + RWARPS - 1) / RWARPS);
    reduce_kernel<<<gr, RWARPS * 32>>>(dz + 0 * (size_t)ROWSK, logits, 0, x2);
    reduce_kernel<<<gr, RWARPS * 32>>>(dz + 1 * (size_t)ROWSK, logits, 1, out);

    // 4) network 2 on x2
    dim3 g2(148, 1);
    mlp_tc<<<g2, MLP_T, SMEM_ALLOC>>>(x2, 2,
                                      iW0, ib0, iW1, ib1, iW2, ib2, iW3, ib3, dz);

    // 5) reduce k=2 -> y2
    reduce_kernel<<<gr, RWARPS * 32>>>(dz + 2 * (size_t)ROWSK, x2, 2, out + NS);

    // 6) pass-through logits
    cudaMemcpyAsync(out + 2 * NS, logits, NS * sizeof(float), cudaMemcpyDeviceToDevice);
}

// round 8
// speedup vs baseline: 6.5235x; 2.1511x over previous
#include <cuda_runtime.h>
#include <cuda_fp16.h>
#include <math.h>
#include <stdint.h>

#define NS 16384
#define NB 100
#define NQ 101
#define HID 100
#define ROWSK (NS * NQ)        // 1654784
#define TILEM 128
#define NTILES (ROWSK / TILEM) // 12928 exactly
#define KP 112                 // padded K (7 chunks of 16)
#define NKC 7
#define PITCH 240              // bytes per smem row (112*2 + 16 pad) -> LDSM conflict-free
#define MLP_T 256

typedef unsigned int u32;

// ---- smem layout (byte offsets) ---------------------------------------------
#define AB (TILEM * PITCH)         // 30720
#define OFF_A    0
#define OFF_W1   (AB)
#define OFF_W2   (2 * AB)
#define OFF_RED  (3 * AB)
#define OFF_VEC  (OFF_RED + 2048)  // b1[128] b2[128] w3[128] w0[128] b0[128]
#define SMEM_ALLOC (OFF_VEC + 5 * 128 * 4 + 256)   // ~97 KB -> 2 CTAs/SM

// ---------------- device globals (scratch) -----------------------------------
__device__ float g_ccw[NQ];
__device__ float g_csc[NQ];
__device__ float g_oh[3][2];
__device__ float g_dz[3][ROWSK];
__device__ float g_x2[NS];

// ---------------- PTX helpers (base-ISA only: ldmatrix + mma.sync) -----------
__device__ __forceinline__ u32 smem_u32(const void* p) {
    u32 a;
    asm("{ .reg .u64 t; cvta.to.shared.u64 t, %1; cvt.u32.u64 %0, t; }" : "=r"(a) : "l"(p));
    return a;
}
__device__ __forceinline__ void ldsm4(u32* r, u32 a) {
    asm volatile("ldmatrix.sync.aligned.m8n8.x4.shared.b16 {%0,%1,%2,%3}, [%4];"
                 : "=r"(r[0]), "=r"(r[1]), "=r"(r[2]), "=r"(r[3]) : "r"(a));
}
__device__ __forceinline__ void ldsm2(u32* r, u32 a) {
    asm volatile("ldmatrix.sync.aligned.m8n8.x2.shared.b16 {%0,%1}, [%2];"
                 : "=r"(r[0]), "=r"(r[1]) : "r"(a));
}
__device__ __forceinline__ void mma16816(float* c, const u32* a, const u32* b) {
    asm volatile("mma.sync.aligned.m16n8k16.row.col.f32.f16.f16.f32 "
                 "{%0,%1,%2,%3}, {%4,%5,%6,%7}, {%8,%9}, {%0,%1,%2,%3};"
                 : "+f"(c[0]), "+f"(c[1]), "+f"(c[2]), "+f"(c[3])
                 : "r"(a[0]), "r"(a[1]), "r"(a[2]), "r"(a[3]), "r"(b[0]), "r"(b[1]));
}

__device__ __forceinline__ unsigned short h_bits(float f) {
    __half h = __float2half_rn(f);
    return *reinterpret_cast<unsigned short*>(&h);
}
__device__ __forceinline__ u32 pack_hi(float f0, float f1) {
    return (u32)h_bits(f0) | ((u32)h_bits(f1) << 16);
}

// ---------------- setup: CC quadrature (fp64) + oh constants -----------------
__global__ void setup_kernel(const float* __restrict__ hb0,
                             const float* __restrict__ hW1,
                             const float* __restrict__ hb1,
                             const float* __restrict__ hW2,
                             const float* __restrict__ hb2,
                             const float* __restrict__ hW3,
                             const float* __restrict__ hb3)
{
    const double PI = 3.14159265358979323846;
    int t = threadIdx.x;
    if (t < NQ) {
        double acc = 0.0;
        for (int i = 0; i <= NB; i++) {
            double lij = cos((double)i * (double)t * PI / (double)NB);
            if (t == 0)  lij = 0.5;
            if (t == NB) lij *= 0.5;
            double Wi;
            if (i == 0)      Wi = 1.0;
            else if (i & 1)  Wi = 0.0;
            else             Wi = 2.0 / (1.0 - (double)i * (double)i);
            acc += lij * Wi;
        }
        g_ccw[t] = (float)(acc * 2.0 / (double)NB);
        g_csc[t] = (float)((cos((double)t * PI / (double)NB) + 1.0) * 0.5);
    }
    __shared__ float hA[HID], hB[HID];
    for (int k = 0; k < 3; k++) {
        if (t < HID) hA[t] = fmaxf(hb0[k * HID + t], 0.f);
        __syncthreads();
        if (t < HID) {
            float s = hb1[k * HID + t];
            for (int i = 0; i < HID; i++) s += hW1[(k * HID + t) * HID + i] * hA[i];
            hB[t] = fmaxf(s, 0.f);
        }
        __syncthreads();
        if (t < HID) {
            float s = hb2[k * HID + t];
            for (int i = 0; i < HID; i++) s += hW2[(k * HID + t) * HID + i] * hB[i];
            hA[t] = fmaxf(s, 0.f);
        }
        __syncthreads();
        if (t < 2) {
            float s = hb3[k * 2 + t];
            for (int i = 0; i < HID; i++) s += hW3[(k * 2 + t) * HID + i] * hA[i];
            g_oh[k][t] = s;
        }
        __syncthreads();
    }
}

// ---------------- tensor-core MLP kernel (fp16 mma.sync, 2 CTAs/SM) ----------
// Warp grid: 2 (M) x 4 (N).  N = 13 n8-tiles, partitioned 4/3/3/3 per wn.
// Plain fp16 quantization of A and W (single product), fp32 accumulate.
__global__ __launch_bounds__(MLP_T, 2)
void mlp_tc(const float* __restrict__ xin, int kbase,
            const float* __restrict__ iW0, const float* __restrict__ ib0,
            const float* __restrict__ iW1, const float* __restrict__ ib1,
            const float* __restrict__ iW2, const float* __restrict__ ib2,
            const float* __restrict__ iW3, const float* __restrict__ ib3,
            float* __restrict__ dzbase)
{
    extern __shared__ char ab[];
    const u32 sm = smem_u32(ab);

    const int tid  = threadIdx.x;
    const int lane = tid & 31;
    const int wid  = tid >> 5;
    const int wm   = wid >> 2;   // 0..1  (M group)
    const int wn   = wid & 3;    // 0..3  (N group)
    const int k    = kbase + blockIdx.y;

    // N-tile partition: wn0 -> tiles [0,4), wn1 -> [4,7), wn2 -> [7,10), wn3 -> [10,13)
    const int nt0  = (wn == 0) ? 0 : (1 + 3 * wn);
    const int ncnt = (wn == 0) ? 4 : 3;

    // zero A + W buffers (establishes K/N pads)
    for (int i = tid; i < (3 * AB) / 16; i += MLP_T)
        reinterpret_cast<uint4*>(ab)[i] = make_uint4(0, 0, 0, 0);

    float* redv = (float*)(ab + OFF_RED);
    float* b1v  = (float*)(ab + OFF_VEC);
    float* b2v  = b1v + 128;
    float* w3v  = b2v + 128;
    float* w0v  = w3v + 128;
    float* b0v  = w0v + 128;
    __syncthreads();

    for (int i = tid; i < 128; i += MLP_T) {
        b1v[i] = (i < HID) ? ib1[k * HID + i] : 0.f;
        b2v[i] = (i < HID) ? ib2[k * HID + i] : 0.f;
        w3v[i] = (i < HID) ? iW3[k * HID + i] : 0.f;
        w0v[i] = (i < HID) ? iW0[(k * HID + i) * 3] : 0.f;  // h==0: input col 0 only
        b0v[i] = (i < HID) ? ib0[k * HID + i] : 0.f;
    }
    // stage W1/W2 (fp16) as [N][K], pitch 240B
    for (int idx = tid; idx < HID * HID; idx += MLP_T) {
        int o = idx / HID, i = idx % HID;
        u32 off = o * PITCH + i * 2;
        *(unsigned short*)(ab + OFF_W1 + off) = h_bits(iW1[(k * HID + o) * HID + i]);
        *(unsigned short*)(ab + OFF_W2 + off) = h_bits(iW2[(k * HID + o) * HID + i]);
    }
    __syncthreads();

    // lane-dependent ldmatrix address terms
    const u32 a_l = (u32)((lane & 15) * PITCH + ((lane >> 4) & 1) * 16);
    const u32 b_l = (u32)((lane & 7) * PITCH + ((lane >> 3) & 1) * 16);
    const u32 sA = sm + OFF_A;

    const float b3 = ib3[k];

    for (int tile = blockIdx.x; tile < NTILES; tile += gridDim.x) {
        // ---- layer 0: scalar -> 100, fp16 into A ----
        {
            int r0 = tid >> 1;
            int row = tile * TILEM + r0;
            int n = row / NQ, j = row - n * NQ;
            float sv = xin[n] * g_csc[j];
            int cbase = (tid & 1) * 50;
            char* a0 = ab + OFF_A + r0 * PITCH;
            #pragma unroll
            for (int p = 0; p < 25; p++) {
                int c = cbase + 2 * p;
                float v0 = fmaxf(fmaf(w0v[c], sv, b0v[c]), 0.f);
                float v1 = fmaxf(fmaf(w0v[c + 1], sv, b0v[c + 1]), 0.f);
                *(u32*)(a0 + c * 2) = pack_hi(v0, v1);
            }
        }
        __syncthreads();

        // ---- layers 1 & 2 via mma.sync ----
        for (int L = 0; L < 2; L++) {
            const u32 sW = sm + (L ? OFF_W2 : OFF_W1);

            float acc[4][4][4];
            #pragma unroll
            for (int mi = 0; mi < 4; mi++)
                #pragma unroll
                for (int ni = 0; ni < 4; ni++)
                    #pragma unroll
                    for (int e = 0; e < 4; e++) acc[mi][ni][e] = 0.f;

            for (int kc = 0; kc < NKC; kc++) {
                u32 ah[4][4], bh[4][2];
                #pragma unroll
                for (int mi = 0; mi < 4; mi++) {
                    u32 aoff = (u32)((wm * 4 + mi) * (16 * PITCH) + kc * 32) + a_l;
                    ldsm4(ah[mi], sA + aoff);
                }
                #pragma unroll
                for (int ni = 0; ni < 4; ni++) {
                    if (ni < ncnt) {
                        u32 boff = (u32)((nt0 + ni) * (8 * PITCH) + kc * 32) + b_l;
                        ldsm2(bh[ni], sW + boff);
                    }
                }
                #pragma unroll
                for (int mi = 0; mi < 4; mi++)
                    #pragma unroll
                    for (int ni = 0; ni < 4; ni++)
                        if (ni < ncnt)
                            mma16816(acc[mi][ni], ah[mi], bh[ni]);
            }
            __syncthreads();   // all A reads complete before overwrite

            if (L == 0) {
                // epilogue: bias + relu, fp16, write back to A
                #pragma unroll
                for (int mi = 0; mi < 4; mi++) {
                    int r0 = (wm * 4 + mi) * 16 + (lane >> 2);
                    #pragma unroll
                    for (int ni = 0; ni < 4; ni++) {
                        int c0 = (nt0 + ni) * 8 + (lane & 3) * 2;
                        if (ni < ncnt && c0 < HID) {
                            float bb0 = b1v[c0], bb1 = b1v[c0 + 1];
                            float v0 = fmaxf(acc[mi][ni][0] + bb0, 0.f);
                            float v1 = fmaxf(acc[mi][ni][1] + bb1, 0.f);
                            float v2 = fmaxf(acc[mi][ni][2] + bb0, 0.f);
                            float v3 = fmaxf(acc[mi][ni][3] + bb1, 0.f);
                            *(u32*)(ab + OFF_A + r0 * PITCH + c0 * 2)       = pack_hi(v0, v1);
                            *(u32*)(ab + OFF_A + (r0 + 8) * PITCH + c0 * 2) = pack_hi(v2, v3);
                        }
                    }
                }
                __syncthreads();
            } else {
                // layer 3: weighted partial dot per thread, warp shfl, smem reduce
                float rp[4][2];
                #pragma unroll
                for (int mi = 0; mi < 4; mi++) { rp[mi][0] = 0.f; rp[mi][1] = 0.f; }
                #pragma unroll
                for (int ni = 0; ni < 4; ni++) {
                    int c0 = (nt0 + ni) * 8 + (lane & 3) * 2;
                    if (ni < ncnt && c0 < HID) {
                        float bb0 = b2v[c0], bb1 = b2v[c0 + 1];
                        float w30 = w3v[c0], w31 = w3v[c0 + 1];
                        #pragma unroll
                        for (int mi = 0; mi < 4; mi++) {
                            float v0 = fmaxf(acc[mi][ni][0] + bb0, 0.f);
                            float v1 = fmaxf(acc[mi][ni][1] + bb1, 0.f);
                            float v2 = fmaxf(acc[mi][ni][2] + bb0, 0.f);
                            float v3 = fmaxf(acc[mi][ni][3] + bb1, 0.f);
                            rp[mi][0] = fmaf(w30, v0, fmaf(w31, v1, rp[mi][0]));
                            rp[mi][1] = fmaf(w30, v2, fmaf(w31, v3, rp[mi][1]));
                        }
                    }
                }
                #pragma unroll
                for (int mi = 0; mi < 4; mi++) {
                    #pragma unroll
                    for (int e = 0; e < 2; e++) {
                        rp[mi][e] += __shfl_xor_sync(0xffffffffu, rp[mi][e], 1);
                        rp[mi][e] += __shfl_xor_sync(0xffffffffu, rp[mi][e], 2);
                    }
                }
                if ((lane & 3) == 0) {
                    #pragma unroll
                    for (int mi = 0; mi < 4; mi++) {
                        int r0 = (wm * 4 + mi) * 16 + (lane >> 2);
                        redv[r0 * 4 + wn] = rp[mi][0];
                        redv[(r0 + 8) * 4 + wn] = rp[mi][1];
                    }
                }
                __syncthreads();
                if (tid < TILEM) {
                    int row = tile * TILEM + tid;
                    int j = row % NQ;
                    float out = redv[tid * 4] + redv[tid * 4 + 1]
                              + redv[tid * 4 + 2] + redv[tid * 4 + 3] + b3;
                    float dz = (out > 0.f) ? (out + 1.f) : expf(out);
                    dzbase[(size_t)k * ROWSK + row] = dz * g_ccw[j];
                }
                __syncthreads();
            }
        }
    }
}

// ---------------- reduction: warp per sample ---------------------------------
__global__ void reduce_kernel(const float* __restrict__ dzk,
                              const float* __restrict__ xin,
                              int k,
                              float* __restrict__ dst)
{
    int n = blockIdx.x * (blockDim.x >> 5) + (threadIdx.x >> 5);
    int lane = threadIdx.x & 31;
    if (n >= NS) return;
    const float* p = dzk + (size_t)n * NQ;
    float s = 0.f;
    for (int j = lane; j < NQ; j += 32) s += p[j];
    #pragma unroll
    for (int o = 16; o; o >>= 1) s += __shfl_xor_sync(0xffffffffu, s, o);
    if (lane == 0) {
        float z = s * xin[n] * 0.5f;
        dst[n] = expf(g_oh[k][1]) * z + g_oh[k][0];
    }
}

// ---------------- launch -----------------------------------------------------
extern "C" void kernel_launch(void* const* d_in, const int* in_sizes, int n_in,
                              void* d_out, int out_size)
{
    const float* logits = (const float*)d_in[0];
    const float* iW0 = (const float*)d_in[2];
    const float* ib0 = (const float*)d_in[3];
    const float* iW1 = (const float*)d_in[4];
    const float* ib1 = (const float*)d_in[5];
    const float* iW2 = (const float*)d_in[6];
    const float* ib2 = (const float*)d_in[7];
    const float* iW3 = (const float*)d_in[8];
    const float* ib3 = (const float*)d_in[9];
    const float* hb0 = (const float*)d_in[11];
    const float* hW1 = (const float*)d_in[12];
    const float* hb1 = (const float*)d_in[13];
    const float* hW2 = (const float*)d_in[14];
    const float* hb2 = (const float*)d_in[15];
    const float* hW3 = (const float*)d_in[16];
    const float* hb3 = (const float*)d_in[17];

    float* out = (float*)d_out;

    void *dz_addr = nullptr, *x2_addr = nullptr;
    cudaGetSymbolAddress(&dz_addr, g_dz);
    cudaGetSymbolAddress(&x2_addr, g_x2);
    float* dz = (float*)dz_addr;
    float* x2 = (float*)x2_addr;

    cudaFuncSetAttribute(mlp_tc, cudaFuncAttributeMaxDynamicSharedMemorySize, SMEM_ALLOC);

    // 1) constants
    setup_kernel<<<1, 128>>>(hb0, hW1, hb1, hW2, hb2, hW3, hb3);

    // 2) networks 0 and 1 on x1 = logits (2 CTAs/SM resident)
    dim3 g1(148, 2);
    mlp_tc<<<g1, MLP_T, SMEM_ALLOC>>>(logits, 0,
                                      iW0, ib0, iW1, ib1, iW2, ib2, iW3, ib3, dz);

    // 3) reduce k=0 -> x2 ; k=1 -> y1
    const int RWARPS = 8;
    dim3 gr((NS + RWARPS - 1) / RWARPS);
    reduce_kernel<<<gr, RWARPS * 32>>>(dz + 0 * (size_t)ROWSK, logits, 0, x2);
    reduce_kernel<<<gr, RWARPS * 32>>>(dz + 1 * (size_t)ROWSK, logits, 1, out);

    // 4) network 2 on x2 (fill both CTA slots per SM)
    dim3 g2(296, 1);
    mlp_tc<<<g2, MLP_T, SMEM_ALLOC>>>(x2, 2,
                                      iW0, ib0, iW1, ib1, iW2, ib2, iW3, ib3, dz);

    // 5) reduce k=2 -> y2
    reduce_kernel<<<gr, RWARPS * 32>>>(dz + 2 * (size_t)ROWSK, x2, 2, out + NS);

    // 6) pass-through logits
    cudaMemcpyAsync(out + 2 * NS, logits, NS * sizeof(float), cudaMemcpyDeviceToDevice);
}

// round 9
// speedup vs baseline: 7.4062x; 1.1353x over previous
#include <cuda_runtime.h>
#include <cuda_fp16.h>
#include <math.h>
#include <stdint.h>

#define NS 16384
#define NB 100
#define NQ 101
#define HID 100
#define ROWSK (NS * NQ)        // 1654784
#define TILEM 128
#define NTILES (ROWSK / TILEM) // 12928 exactly
#define KP 112                 // padded K (7 chunks of 16)
#define NKC 7
#define PITCH 240              // bytes per smem row (112*2 + 16 pad) -> LDSM conflict-free
#define MLP_T 256

typedef unsigned int u32;

// ---- smem layout (byte offsets) ---------------------------------------------
#define AB (TILEM * PITCH)         // 30720
#define OFF_A    0
#define OFF_W1   (AB)
#define OFF_W2   (2 * AB)
#define OFF_RED  (3 * AB)          // 2 parity buffers x 2048 B
#define OFF_VEC  (OFF_RED + 4096)  // b1[128] b2[128] w3[128] w0[128] b0[128]
#define SMEM_ALLOC (OFF_VEC + 5 * 128 * 4 + 256)   // ~99 KB -> 2 CTAs/SM

// ---------------- device globals (scratch) -----------------------------------
__device__ float g_ccw[NQ];
__device__ float g_csc[NQ];
__device__ float g_oh[3][2];
__device__ float g_dz[3][ROWSK];
__device__ float g_x2[NS];

// ---------------- PTX helpers (base-ISA only: ldmatrix + mma.sync) -----------
__device__ __forceinline__ u32 smem_u32(const void* p) {
    u32 a;
    asm("{ .reg .u64 t; cvta.to.shared.u64 t, %1; cvt.u32.u64 %0, t; }" : "=r"(a) : "l"(p));
    return a;
}
__device__ __forceinline__ void ldsm4(u32* r, u32 a) {
    asm volatile("ldmatrix.sync.aligned.m8n8.x4.shared.b16 {%0,%1,%2,%3}, [%4];"
                 : "=r"(r[0]), "=r"(r[1]), "=r"(r[2]), "=r"(r[3]) : "r"(a));
}
__device__ __forceinline__ void ldsm2(u32* r, u32 a) {
    asm volatile("ldmatrix.sync.aligned.m8n8.x2.shared.b16 {%0,%1}, [%2];"
                 : "=r"(r[0]), "=r"(r[1]) : "r"(a));
}
__device__ __forceinline__ void mma16816(float* c, const u32* a, const u32* b) {
    asm volatile("mma.sync.aligned.m16n8k16.row.col.f32.f16.f16.f32 "
                 "{%0,%1,%2,%3}, {%4,%5,%6,%7}, {%8,%9}, {%0,%1,%2,%3};"
                 : "+f"(c[0]), "+f"(c[1]), "+f"(c[2]), "+f"(c[3])
                 : "r"(a[0]), "r"(a[1]), "r"(a[2]), "r"(a[3]), "r"(b[0]), "r"(b[1]));
}
// half-CTA barrier: 128 threads of one wm group (threads 0-127 or 128-255)
__device__ __forceinline__ void bar_half(int wm) {
    asm volatile("bar.sync %0, 128;" :: "r"(1 + wm) : "memory");
}

__device__ __forceinline__ unsigned short h_bits(float f) {
    __half h = __float2half_rn(f);
    return *reinterpret_cast<unsigned short*>(&h);
}
__device__ __forceinline__ u32 pack_hi(float f0, float f1) {
    return (u32)h_bits(f0) | ((u32)h_bits(f1) << 16);
}

// ---------------- setup: 4 blocks (CC quadrature + 3x oh constants) ----------
__global__ void setup_kernel(const float* __restrict__ hb0,
                             const float* __restrict__ hW1,
                             const float* __restrict__ hb1,
                             const float* __restrict__ hW2,
                             const float* __restrict__ hb2,
                             const float* __restrict__ hW3,
                             const float* __restrict__ hb3)
{
    const double PI = 3.14159265358979323846;
    int t = threadIdx.x;

    if (blockIdx.x == 0) {
        if (t < NQ) {
            double acc = 0.0;
            for (int i = 0; i <= NB; i++) {
                double lij = cos((double)i * (double)t * PI / (double)NB);
                if (t == 0)  lij = 0.5;
                if (t == NB) lij *= 0.5;
                double Wi;
                if (i == 0)      Wi = 1.0;
                else if (i & 1)  Wi = 0.0;
                else             Wi = 2.0 / (1.0 - (double)i * (double)i);
                acc += lij * Wi;
            }
            g_ccw[t] = (float)(acc * 2.0 / (double)NB);
            g_csc[t] = (float)((cos((double)t * PI / (double)NB) + 1.0) * 0.5);
        }
        return;
    }

    // blocks 1..3: oh_k = MLP_h(0) for k = blockIdx.x - 1
    int k = blockIdx.x - 1;
    __shared__ float hA[HID], hB[HID];
    if (t < HID) hA[t] = fmaxf(hb0[k * HID + t], 0.f);
    __syncthreads();
    if (t < HID) {
        float s = hb1[k * HID + t];
        for (int i = 0; i < HID; i++) s += hW1[(k * HID + t) * HID + i] * hA[i];
        hB[t] = fmaxf(s, 0.f);
    }
    __syncthreads();
    if (t < HID) {
        float s = hb2[k * HID + t];
        for (int i = 0; i < HID; i++) s += hW2[(k * HID + t) * HID + i] * hB[i];
        hA[t] = fmaxf(s, 0.f);
    }
    __syncthreads();
    if (t < 2) {
        float s = hb3[k * 2 + t];
        for (int i = 0; i < HID; i++) s += hW3[(k * 2 + t) * HID + i] * hA[i];
        g_oh[k][t] = s;
    }
}

// ---------------- tensor-core MLP kernel (fp16 mma.sync, 2 CTAs/SM) ----------
// Warp grid: 2 (M) x 4 (N).  N = 13 n8-tiles, partitioned 4/3/3/3 per wn.
// Half-CTA named barriers for A-tile ordering (rows partitioned by wm).
__global__ __launch_bounds__(MLP_T, 2)
void mlp_tc(const float* __restrict__ xin, int kbase,
            const float* __restrict__ iW0, const float* __restrict__ ib0,
            const float* __restrict__ iW1, const float* __restrict__ ib1,
            const float* __restrict__ iW2, const float* __restrict__ ib2,
            const float* __restrict__ iW3, const float* __restrict__ ib3,
            float* __restrict__ dzbase)
{
    extern __shared__ char ab[];
    const u32 sm = smem_u32(ab);

    const int tid  = threadIdx.x;
    const int lane = tid & 31;
    const int wid  = tid >> 5;
    const int wm   = wid >> 2;   // 0..1  (M group; threads [wm*128, wm*128+128))
    const int wn   = wid & 3;    // 0..3  (N group)
    const int k    = kbase + blockIdx.y;

    // N-tile partition: wn0 -> tiles [0,4), wn1 -> [4,7), wn2 -> [7,10), wn3 -> [10,13)
    const int nt0  = (wn == 0) ? 0 : (1 + 3 * wn);
    const int ncnt = (wn == 0) ? 4 : 3;

    // zero A + W buffers (establishes K/N pads)
    for (int i = tid; i < (3 * AB) / 16; i += MLP_T)
        reinterpret_cast<uint4*>(ab)[i] = make_uint4(0, 0, 0, 0);

    float* redv = (float*)(ab + OFF_RED);   // [2][128][4]
    float* b1v  = (float*)(ab + OFF_VEC);
    float* b2v  = b1v + 128;
    float* w3v  = b2v + 128;
    float* w0v  = w3v + 128;
    float* b0v  = w0v + 128;
    __syncthreads();

    for (int i = tid; i < 128; i += MLP_T) {
        b1v[i] = (i < HID) ? ib1[k * HID + i] : 0.f;
        b2v[i] = (i < HID) ? ib2[k * HID + i] : 0.f;
        w3v[i] = (i < HID) ? iW3[k * HID + i] : 0.f;
        w0v[i] = (i < HID) ? iW0[(k * HID + i) * 3] : 0.f;  // h==0: input col 0 only
        b0v[i] = (i < HID) ? ib0[k * HID + i] : 0.f;
    }
    // stage W1/W2 (fp16) as [N][K], pitch 240B
    for (int idx = tid; idx < HID * HID; idx += MLP_T) {
        int o = idx / HID, i = idx % HID;
        u32 off = o * PITCH + i * 2;
        *(unsigned short*)(ab + OFF_W1 + off) = h_bits(iW1[(k * HID + o) * HID + i]);
        *(unsigned short*)(ab + OFF_W2 + off) = h_bits(iW2[(k * HID + o) * HID + i]);
    }
    __syncthreads();

    // lane-dependent ldmatrix address terms
    const u32 a_l = (u32)((lane & 15) * PITCH + ((lane >> 4) & 1) * 16);
    const u32 b_l = (u32)((lane & 7) * PITCH + ((lane >> 3) & 1) * 16);
    const u32 sA = sm + OFF_A;

    const float b3 = ib3[k];

    int par = 0;
    for (int tile = blockIdx.x; tile < NTILES; tile += gridDim.x, par ^= 1) {
        float* redp = redv + par * 512;

        // ---- layer 0: scalar -> 100, fp16 into A (own half rows) ----
        {
            int r0 = tid >> 1;
            int row = tile * TILEM + r0;
            int n = row / NQ, j = row - n * NQ;
            float sv = xin[n] * g_csc[j];
            int cbase = (tid & 1) * 50;
            char* a0 = ab + OFF_A + r0 * PITCH;
            #pragma unroll
            for (int p = 0; p < 25; p++) {
                int c = cbase + 2 * p;
                float v0 = fmaxf(fmaf(w0v[c], sv, b0v[c]), 0.f);
                float v1 = fmaxf(fmaf(w0v[c + 1], sv, b0v[c + 1]), 0.f);
                *(u32*)(a0 + c * 2) = pack_hi(v0, v1);
            }
        }
        bar_half(wm);   // rows of this half ready for this half's ldsm

        // ---- layers 1 & 2 via mma.sync ----
        for (int L = 0; L < 2; L++) {
            const u32 sW = sm + (L ? OFF_W2 : OFF_W1);

            float acc[4][4][4];
            #pragma unroll
            for (int mi = 0; mi < 4; mi++)
                #pragma unroll
                for (int ni = 0; ni < 4; ni++)
                    #pragma unroll
                    for (int e = 0; e < 4; e++) acc[mi][ni][e] = 0.f;

            #pragma unroll
            for (int kc = 0; kc < NKC; kc++) {
                u32 ah[4][4], bh[4][2];
                #pragma unroll
                for (int mi = 0; mi < 4; mi++) {
                    u32 aoff = (u32)((wm * 4 + mi) * (16 * PITCH) + kc * 32) + a_l;
                    ldsm4(ah[mi], sA + aoff);
                }
                #pragma unroll
                for (int ni = 0; ni < 4; ni++) {
                    if (ni < ncnt) {
                        u32 boff = (u32)((nt0 + ni) * (8 * PITCH) + kc * 32) + b_l;
                        ldsm2(bh[ni], sW + boff);
                    }
                }
                #pragma unroll
                for (int mi = 0; mi < 4; mi++)
                    #pragma unroll
                    for (int ni = 0; ni < 4; ni++)
                        if (ni < ncnt)
                            mma16816(acc[mi][ni], ah[mi], bh[ni]);
            }

            if (L == 0) {
                bar_half(wm);   // this half's A reads complete before overwrite
                // epilogue: bias + relu, fp16, write back to A (own half rows)
                #pragma unroll
                for (int mi = 0; mi < 4; mi++) {
                    int r0 = (wm * 4 + mi) * 16 + (lane >> 2);
                    #pragma unroll
                    for (int ni = 0; ni < 4; ni++) {
                        int c0 = (nt0 + ni) * 8 + (lane & 3) * 2;
                        if (ni < ncnt && c0 < HID) {
                            float bb0 = b1v[c0], bb1 = b1v[c0 + 1];
                            float v0 = fmaxf(acc[mi][ni][0] + bb0, 0.f);
                            float v1 = fmaxf(acc[mi][ni][1] + bb1, 0.f);
                            float v2 = fmaxf(acc[mi][ni][2] + bb0, 0.f);
                            float v3 = fmaxf(acc[mi][ni][3] + bb1, 0.f);
                            *(u32*)(ab + OFF_A + r0 * PITCH + c0 * 2)       = pack_hi(v0, v1);
                            *(u32*)(ab + OFF_A + (r0 + 8) * PITCH + c0 * 2) = pack_hi(v2, v3);
                        }
                    }
                }
                bar_half(wm);   // A ready for this half's L2 ldsm
            } else {
                // layer 3: weighted partial dot per thread, warp shfl, smem reduce
                float rp[4][2];
                #pragma unroll
                for (int mi = 0; mi < 4; mi++) { rp[mi][0] = 0.f; rp[mi][1] = 0.f; }
                #pragma unroll
                for (int ni = 0; ni < 4; ni++) {
                    int c0 = (nt0 + ni) * 8 + (lane & 3) * 2;
                    if (ni < ncnt && c0 < HID) {
                        float bb0 = b2v[c0], bb1 = b2v[c0 + 1];
                        float w30 = w3v[c0], w31 = w3v[c0 + 1];
                        #pragma unroll
                        for (int mi = 0; mi < 4; mi++) {
                            float v0 = fmaxf(acc[mi][ni][0] + bb0, 0.f);
                            float v1 = fmaxf(acc[mi][ni][1] + bb1, 0.f);
                            float v2 = fmaxf(acc[mi][ni][2] + bb0, 0.f);
                            float v3 = fmaxf(acc[mi][ni][3] + bb1, 0.f);
                            rp[mi][0] = fmaf(w30, v0, fmaf(w31, v1, rp[mi][0]));
                            rp[mi][1] = fmaf(w30, v2, fmaf(w31, v3, rp[mi][1]));
                        }
                    }
                }
                #pragma unroll
                for (int mi = 0; mi < 4; mi++) {
                    #pragma unroll
                    for (int e = 0; e < 2; e++) {
                        rp[mi][e] += __shfl_xor_sync(0xffffffffu, rp[mi][e], 1);
                        rp[mi][e] += __shfl_xor_sync(0xffffffffu, rp[mi][e], 2);
                    }
                }
                if ((lane & 3) == 0) {
                    #pragma unroll
                    for (int mi = 0; mi < 4; mi++) {
                        int r0 = (wm * 4 + mi) * 16 + (lane >> 2);
                        redp[r0 * 4 + wn] = rp[mi][0];
                        redp[(r0 + 8) * 4 + wn] = rp[mi][1];
                    }
                }
                __syncthreads();   // redv complete; also: all A reads of this tile done
                if (tid < TILEM) {
                    int row = tile * TILEM + tid;
                    int j = row % NQ;
                    float out = redp[tid * 4] + redp[tid * 4 + 1]
                              + redp[tid * 4 + 2] + redp[tid * 4 + 3] + b3;
                    float dz = (out > 0.f) ? (out + 1.f) : expf(out);
                    dzbase[(size_t)k * ROWSK + row] = dz * g_ccw[j];
                }
                // no trailing sync: redv parity buffer protects reuse
            }
        }
    }
}

// ---------------- reduction: warp per sample ---------------------------------
__global__ void reduce_kernel(const float* __restrict__ dzk,
                              const float* __restrict__ xin,
                              int k,
                              float* __restrict__ dst)
{
    int n = blockIdx.x * (blockDim.x >> 5) + (threadIdx.x >> 5);
    int lane = threadIdx.x & 31;
    if (n >= NS) return;
    const float* p = dzk + (size_t)n * NQ;
    float s = 0.f;
    for (int j = lane; j < NQ; j += 32) s += p[j];
    #pragma unroll
    for (int o = 16; o; o >>= 1) s += __shfl_xor_sync(0xffffffffu, s, o);
    if (lane == 0) {
        float z = s * xin[n] * 0.5f;
        dst[n] = expf(g_oh[k][1]) * z + g_oh[k][0];
    }
}

// ---------------- launch -----------------------------------------------------
extern "C" void kernel_launch(void* const* d_in, const int* in_sizes, int n_in,
                              void* d_out, int out_size)
{
    const float* logits = (const float*)d_in[0];
    const float* iW0 = (const float*)d_in[2];
    const float* ib0 = (const float*)d_in[3];
    const float* iW1 = (const float*)d_in[4];
    const float* ib1 = (const float*)d_in[5];
    const float* iW2 = (const float*)d_in[6];
    const float* ib2 = (const float*)d_in[7];
    const float* iW3 = (const float*)d_in[8];
    const float* ib3 = (const float*)d_in[9];
    const float* hb0 = (const float*)d_in[11];
    const float* hW1 = (const float*)d_in[12];
    const float* hb1 = (const float*)d_in[13];
    const float* hW2 = (const float*)d_in[14];
    const float* hb2 = (const float*)d_in[15];
    const float* hW3 = (const float*)d_in[16];
    const float* hb3 = (const float*)d_in[17];

    float* out = (float*)d_out;

    void *dz_addr = nullptr, *x2_addr = nullptr;
    cudaGetSymbolAddress(&dz_addr, g_dz);
    cudaGetSymbolAddress(&x2_addr, g_x2);
    float* dz = (float*)dz_addr;
    float* x2 = (float*)x2_addr;

    cudaFuncSetAttribute(mlp_tc, cudaFuncAttributeMaxDynamicSharedMemorySize, SMEM_ALLOC);

    // 1) constants (4 parallel blocks)
    setup_kernel<<<4, 128>>>(hb0, hW1, hb1, hW2, hb2, hW3, hb3);

    // 2) networks 0 and 1 on x1 = logits (2 CTAs/SM resident)
    dim3 g1(148, 2);
    mlp_tc<<<g1, MLP_T, SMEM_ALLOC>>>(logits, 0,
                                      iW0, ib0, iW1, ib1, iW2, ib2, iW3, ib3, dz);

    // 3) reduce k=0 -> x2 ; k=1 -> y1
    const int RWARPS = 8;
    dim3 gr((NS + RWARPS - 1) / RWARPS);
    reduce_kernel<<<gr, RWARPS * 32>>>(dz + 0 * (size_t)ROWSK, logits, 0, x2);
    reduce_kernel<<<gr, RWARPS * 32>>>(dz + 1 * (size_t)ROWSK, logits, 1, out);

    // 4) network 2 on x2 (fill both CTA slots per SM)
    dim3 g2(296, 1);
    mlp_tc<<<g2, MLP_T, SMEM_ALLOC>>>(x2, 2,
                                      iW0, ib0, iW1, ib1, iW2, ib2, iW3, ib3, dz);

    // 5) reduce k=2 -> y2
    reduce_kernel<<<gr, RWARPS * 32>>>(dz + 2 * (size_t)ROWSK, x2, 2, out + NS);

    // 6) pass-through logits
    cudaMemcpyAsync(out + 2 * NS, logits, NS * sizeof(float), cudaMemcpyDeviceToDevice);
}

// round 11
// speedup vs baseline: 7.5899x; 1.0248x over previous
#include <cuda_runtime.h>
#include <cuda_fp16.h>
#include <math.h>
#include <stdint.h>

#define NS 16384
#define NB 100
#define NQ 101
#define HID 100
#define ROWSK (NS * NQ)        // 1654784
#define TILEM 128
#define NTILES (ROWSK / TILEM) // 12928 exactly
#define NKC 6                  // full k16 chunks; +1 k8 tail at col 96
#define PITCH 240              // bytes per smem row (112*2 + 16 pad) -> LDSM conflict-free
#define MLP_T 256

typedef unsigned int u32;

// ---- smem layout (byte offsets) ---------------------------------------------
#define AB (TILEM * PITCH)         // 30720
#define OFF_A    0
#define OFF_W1   (AB)
#define OFF_W2   (2 * AB)
#define OFF_RED  (3 * AB)          // 2 parity buffers x 2048 B
#define OFF_VEC  (OFF_RED + 4096)  // b1[128] b2[128] w3[128] w0[128] b0[128]
#define SMEM_ALLOC (OFF_VEC + 5 * 128 * 4 + 256)   // ~99 KB -> 2 CTAs/SM

// ---------------- device globals (scratch) -----------------------------------
__device__ float g_ccw[NQ];
__device__ float g_csc[NQ];
__device__ float g_oh[3][2];
__device__ float g_dz[3][ROWSK];
__device__ float g_x2[NS];

// ---------------- PTX helpers (base-ISA only: ldmatrix + mma.sync) -----------
__device__ __forceinline__ u32 smem_u32(const void* p) {
    u32 a;
    asm("{ .reg .u64 t; cvta.to.shared.u64 t, %1; cvt.u32.u64 %0, t; }" : "=r"(a) : "l"(p));
    return a;
}
__device__ __forceinline__ void ldsm4(u32* r, u32 a) {
    asm volatile("ldmatrix.sync.aligned.m8n8.x4.shared.b16 {%0,%1,%2,%3}, [%4];"
                 : "=r"(r[0]), "=r"(r[1]), "=r"(r[2]), "=r"(r[3]) : "r"(a));
}
__device__ __forceinline__ void ldsm2(u32* r, u32 a) {
    asm volatile("ldmatrix.sync.aligned.m8n8.x2.shared.b16 {%0,%1}, [%2];"
                 : "=r"(r[0]), "=r"(r[1]) : "r"(a));
}
__device__ __forceinline__ void ldsm1(u32* r, u32 a) {
    asm volatile("ldmatrix.sync.aligned.m8n8.x1.shared.b16 {%0}, [%1];"
                 : "=r"(r[0]) : "r"(a));
}
__device__ __forceinline__ void mma16816(float* c, const u32* a, const u32* b) {
    asm volatile("mma.sync.aligned.m16n8k16.row.col.f32.f16.f16.f32 "
                 "{%0,%1,%2,%3}, {%4,%5,%6,%7}, {%8,%9}, {%0,%1,%2,%3};"
                 : "+f"(c[0]), "+f"(c[1]), "+f"(c[2]), "+f"(c[3])
                 : "r"(a[0]), "r"(a[1]), "r"(a[2]), "r"(a[3]), "r"(b[0]), "r"(b[1]));
}
__device__ __forceinline__ void mma1688(float* c, const u32* a, const u32* b) {
    asm volatile("mma.sync.aligned.m16n8k8.row.col.f32.f16.f16.f32 "
                 "{%0,%1,%2,%3}, {%4,%5}, {%6}, {%0,%1,%2,%3};"
                 : "+f"(c[0]), "+f"(c[1]), "+f"(c[2]), "+f"(c[3])
                 : "r"(a[0]), "r"(a[1]), "r"(b[0]));
}
// half-CTA barrier: 128 threads of one wm group (threads 0-127 or 128-255)
__device__ __forceinline__ void bar_half(int wm) {
    asm volatile("bar.sync %0, 128;" :: "r"(1 + wm) : "memory");
}

__device__ __forceinline__ unsigned short h_bits(float f) {
    __half h = __float2half_rn(f);
    return *reinterpret_cast<unsigned short*>(&h);
}
__device__ __forceinline__ u32 pack_hi(float f0, float f1) {
    return (u32)h_bits(f0) | ((u32)h_bits(f1) << 16);
}

// ---------------- setup: 4 blocks (CC quadrature + 3x oh constants) ----------
__global__ void setup_kernel(const float* __restrict__ hb0,
                             const float* __restrict__ hW1,
                             const float* __restrict__ hb1,
                             const float* __restrict__ hW2,
                             const float* __restrict__ hb2,
                             const float* __restrict__ hW3,
                             const float* __restrict__ hb3)
{
    const double PI = 3.14159265358979323846;
    int t = threadIdx.x;

    if (blockIdx.x == 0) {
        if (t < NQ) {
            double acc = 0.0;
            for (int i = 0; i <= NB; i++) {
                double lij = cos((double)i * (double)t * PI / (double)NB);
                if (t == 0)  lij = 0.5;
                if (t == NB) lij *= 0.5;
                double Wi;
                if (i == 0)      Wi = 1.0;
                else if (i & 1)  Wi = 0.0;
                else             Wi = 2.0 / (1.0 - (double)i * (double)i);
                acc += lij * Wi;
            }
            g_ccw[t] = (float)(acc * 2.0 / (double)NB);
            g_csc[t] = (float)((cos((double)t * PI / (double)NB) + 1.0) * 0.5);
        }
        return;
    }

    int k = blockIdx.x - 1;
    __shared__ float hA[HID], hB[HID];
    if (t < HID) hA[t] = fmaxf(hb0[k * HID + t], 0.f);
    __syncthreads();
    if (t < HID) {
        float s = hb1[k * HID + t];
        for (int i = 0; i < HID; i++) s += hW1[(k * HID + t) * HID + i] * hA[i];
        hB[t] = fmaxf(s, 0.f);
    }
    __syncthreads();
    if (t < HID) {
        float s = hb2[k * HID + t];
        for (int i = 0; i < HID; i++) s += hW2[(k * HID + t) * HID + i] * hB[i];
        hA[t] = fmaxf(s, 0.f);
    }
    __syncthreads();
    if (t < 2) {
        float s = hb3[k * 2 + t];
        for (int i = 0; i < HID; i++) s += hW3[(k * 2 + t) * HID + i] * hA[i];
        g_oh[k][t] = s;
    }
}

// ---------------- tensor-core MLP kernel (fp16 mma.sync, 2 CTAs/SM) ----------
// Warp grid: 2 (M) x 4 (N).  N = 13 n8-tiles; partition index rotates with
// (wn + wm + 2L) & 3 to balance HMMA load across SMSPs (wid&3 = SMSP).
// K: 6 x k16 chunks + 1 x k8 tail (cols 96..103; 100..103 zero).
__global__ __launch_bounds__(MLP_T, 2)
void mlp_tc(const float* __restrict__ xin, int kbase,
            const float* __restrict__ iW0, const float* __restrict__ ib0,
            const float* __restrict__ iW1, const float* __restrict__ ib1,
            const float* __restrict__ iW2, const float* __restrict__ ib2,
            const float* __restrict__ iW3, const float* __restrict__ ib3,
            float* __restrict__ dzbase)
{
    extern __shared__ char ab[];
    const u32 sm = smem_u32(ab);

    const int tid  = threadIdx.x;
    const int lane = tid & 31;
    const int wid  = tid >> 5;
    const int wm   = wid >> 2;   // 0..1  (M group; threads [wm*128, wm*128+128))
    const int wn   = wid & 3;    // 0..3  (SMSP index)
    const int k    = kbase + blockIdx.y;

    // zero A + W buffers (establishes K/N pads)
    for (int i = tid; i < (3 * AB) / 16; i += MLP_T)
        reinterpret_cast<uint4*>(ab)[i] = make_uint4(0, 0, 0, 0);

    float* redv = (float*)(ab + OFF_RED);   // [2][128][4]
    float* b1v  = (float*)(ab + OFF_VEC);
    float* b2v  = b1v + 128;
    float* w3v  = b2v + 128;
    float* w0v  = w3v + 128;
    float* b0v  = w0v + 128;
    __syncthreads();

    for (int i = tid; i < 128; i += MLP_T) {
        b1v[i] = (i < HID) ? ib1[k * HID + i] : 0.f;
        b2v[i] = (i < HID) ? ib2[k * HID + i] : 0.f;
        w3v[i] = (i < HID) ? iW3[k * HID + i] : 0.f;
        w0v[i] = (i < HID) ? iW0[(k * HID + i) * 3] : 0.f;  // h==0: input col 0 only
        b0v[i] = (i < HID) ? ib0[k * HID + i] : 0.f;
    }
    // stage W1/W2 (fp16) as [N][K], pitch 240B
    for (int idx = tid; idx < HID * HID; idx += MLP_T) {
        int o = idx / HID, i = idx % HID;
        u32 off = o * PITCH + i * 2;
        *(unsigned short*)(ab + OFF_W1 + off) = h_bits(iW1[(k * HID + o) * HID + i]);
        *(unsigned short*)(ab + OFF_W2 + off) = h_bits(iW2[(k * HID + o) * HID + i]);
    }
    __syncthreads();

    // lane-dependent ldmatrix address terms
    const u32 a_l  = (u32)((lane & 15) * PITCH + ((lane >> 4) & 1) * 16);  // k16 A (x4)
    const u32 a_l2 = (u32)((lane & 15) * PITCH + 192);                     // k8 tail A (x2)
    const u32 b_l  = (u32)((lane & 7) * PITCH + ((lane >> 3) & 1) * 16);   // k16 B (x2)
    const u32 b_l1 = (u32)((lane & 7) * PITCH + 192);                      // k8 tail B (x1)
    const u32 sA = sm + OFF_A;

    const float b3 = ib3[k];

    int par = 0;
    for (int tile = blockIdx.x; tile < NTILES; tile += gridDim.x, par ^= 1) {
        float* redp = redv + par * 512;

        // ---- layer 0: scalar -> 100, fp16 into A (own half rows) ----
        {
            int r0 = tid >> 1;
            int row = tile * TILEM + r0;
            int n = row / NQ, j = row - n * NQ;
            float sv = xin[n] * g_csc[j];
            int cbase = (tid & 1) * 50;
            char* a0 = ab + OFF_A + r0 * PITCH;
            #pragma unroll
            for (int p = 0; p < 25; p++) {
                int c = cbase + 2 * p;
                float v0 = fmaxf(fmaf(w0v[c], sv, b0v[c]), 0.f);
                float v1 = fmaxf(fmaf(w0v[c + 1], sv, b0v[c + 1]), 0.f);
                *(u32*)(a0 + c * 2) = pack_hi(v0, v1);
            }
        }
        bar_half(wm);   // rows of this half ready for this half's ldsm

        // ---- layers 1 & 2 via mma.sync ----
        for (int L = 0; L < 2; L++) {
            const u32 sW = sm + (L ? OFF_W2 : OFF_W1);

            // rotated N-partition for SMSP balance
            const int part = (wn + wm + 2 * L) & 3;
            const int nt0  = (part == 0) ? 0 : (1 + 3 * part);
            const int ncnt = (part == 0) ? 4 : 3;

            float acc[4][4][4];
            #pragma unroll
            for (int mi = 0; mi < 4; mi++)
                #pragma unroll
                for (int ni = 0; ni < 4; ni++)
                    #pragma unroll
                    for (int e = 0; e < 4; e++) acc[mi][ni][e] = 0.f;

            #pragma unroll
            for (int kc = 0; kc < NKC; kc++) {
                u32 ah[4][4], bh[4][2];
                #pragma unroll
                for (int mi = 0; mi < 4; mi++) {
                    u32 aoff = (u32)((wm * 4 + mi) * (16 * PITCH) + kc * 32) + a_l;
                    ldsm4(ah[mi], sA + aoff);
                }
                #pragma unroll
                for (int ni = 0; ni < 4; ni++) {
                    if (ni < ncnt) {
                        u32 boff = (u32)((nt0 + ni) * (8 * PITCH) + kc * 32) + b_l;
                        ldsm2(bh[ni], sW + boff);
                    }
                }
                #pragma unroll
                for (int mi = 0; mi < 4; mi++)
                    #pragma unroll
                    for (int ni = 0; ni < 4; ni++)
                        if (ni < ncnt)
                            mma16816(acc[mi][ni], ah[mi], bh[ni]);
            }
            // k8 tail: cols 96..103 (100..103 are zero padding)
            {
                u32 at[4][2], bt[4][1];
                #pragma unroll
                for (int mi = 0; mi < 4; mi++) {
                    u32 aoff = (u32)((wm * 4 + mi) * (16 * PITCH)) + a_l2;
                    ldsm2(at[mi], sA + aoff);
                }
                #pragma unroll
                for (int ni = 0; ni < 4; ni++) {
                    if (ni < ncnt) {
                        u32 boff = (u32)((nt0 + ni) * (8 * PITCH)) + b_l1;
                        ldsm1(bt[ni], sW + boff);
                    }
                }
                #pragma unroll
                for (int mi = 0; mi < 4; mi++)
                    #pragma unroll
                    for (int ni = 0; ni < 4; ni++)
                        if (ni < ncnt)
                            mma1688(acc[mi][ni], at[mi], bt[ni]);
            }

            if (L == 0) {
                bar_half(wm);   // this half's A reads complete before overwrite
                // epilogue: bias + relu, fp16, write back to A (own half rows)
                #pragma unroll
                for (int mi = 0; mi < 4; mi++) {
                    int r0 = (wm * 4 + mi) * 16 + (lane >> 2);
                    #pragma unroll
                    for (int ni = 0; ni < 4; ni++) {
                        int c0 = (nt0 + ni) * 8 + (lane & 3) * 2;
                        if (ni < ncnt && c0 < HID) {
                            float bb0 = b1v[c0], bb1 = b1v[c0 + 1];
                            float v0 = fmaxf(acc[mi][ni][0] + bb0, 0.f);
                            float v1 = fmaxf(acc[mi][ni][1] + bb1, 0.f);
                            float v2 = fmaxf(acc[mi][ni][2] + bb0, 0.f);
                            float v3 = fmaxf(acc[mi][ni][3] + bb1, 0.f);
                            *(u32*)(ab + OFF_A + r0 * PITCH + c0 * 2)       = pack_hi(v0, v1);
                            *(u32*)(ab + OFF_A + (r0 + 8) * PITCH + c0 * 2) = pack_hi(v2, v3);
                        }
                    }
                }
                bar_half(wm);   // A ready for this half's L2 ldsm
            } else {
                // layer 3: weighted partial dot per thread, warp shfl, smem reduce
                float rp[4][2];
                #pragma unroll
                for (int mi = 0; mi < 4; mi++) { rp[mi][0] = 0.f; rp[mi][1] = 0.f; }
                #pragma unroll
                for (int ni = 0; ni < 4; ni++) {
                    int c0 = (nt0 + ni) * 8 + (lane & 3) * 2;
                    if (ni < ncnt && c0 < HID) {
                        float bb0 = b2v[c0], bb1 = b2v[c0 + 1];
                        float w30 = w3v[c0], w31 = w3v[c0 + 1];
                        #pragma unroll
                        for (int mi = 0; mi < 4; mi++) {
                            float v0 = fmaxf(acc[mi][ni][0] + bb0, 0.f);
                            float v1 = fmaxf(acc[mi][ni][1] + bb1, 0.f);
                            float v2 = fmaxf(acc[mi][ni][2] + bb0, 0.f);
                            float v3 = fmaxf(acc[mi][ni][3] + bb1, 0.f);
                            rp[mi][0] = fmaf(w30, v0, fmaf(w31, v1, rp[mi][0]));
                            rp[mi][1] = fmaf(w30, v2, fmaf(w31, v3, rp[mi][1]));
                        }
                    }
                }
                #pragma unroll
                for (int mi = 0; mi < 4; mi++) {
                    #pragma unroll
                    for (int e = 0; e < 2; e++) {
                        rp[mi][e] += __shfl_xor_sync(0xffffffffu, rp[mi][e], 1);
                        rp[mi][e] += __shfl_xor_sync(0xffffffffu, rp[mi][e], 2);
                    }
                }
                if ((lane & 3) == 0) {
                    #pragma unroll
                    for (int mi = 0; mi < 4; mi++) {
                        int r0 = (wm * 4 + mi) * 16 + (lane >> 2);
                        redp[r0 * 4 + wn] = rp[mi][0];
                        redp[(r0 + 8) * 4 + wn] = rp[mi][1];
                    }
                }
                __syncthreads();   // redv complete; also: all A reads of this tile done
                if (tid < TILEM) {
                    int row = tile * TILEM + tid;
                    int j = row % NQ;
                    float out = redp[tid * 4] + redp[tid * 4 + 1]
                              + redp[tid * 4 + 2] + redp[tid * 4 + 3] + b3;
                    float dz = (out > 0.f) ? (out + 1.f) : expf(out);
                    dzbase[(size_t)k * ROWSK + row] = dz * g_ccw[j];
                }
                // no trailing sync: redv parity buffer protects reuse
            }
        }
    }
}

// ---------------- reduction: warp per sample ---------------------------------
__global__ void reduce_kernel(const float* __restrict__ dzk,
                              const float* __restrict__ xin,
                              int k,
                              float* __restrict__ dst)
{
    int n = blockIdx.x * (blockDim.x >> 5) + (threadIdx.x >> 5);
    int lane = threadIdx.x & 31;
    if (n >= NS) return;
    const float* p = dzk + (size_t)n * NQ;
    float s = 0.f;
    for (int j = lane; j < NQ; j += 32) s += p[j];
    #pragma unroll
    for (int o = 16; o; o >>= 1) s += __shfl_xor_sync(0xffffffffu, s, o);
    if (lane == 0) {
        float z = s * xin[n] * 0.5f;
        dst[n] = expf(g_oh[k][1]) * z + g_oh[k][0];
    }
}

// ---------------- launch -----------------------------------------------------
extern "C" void kernel_launch(void* const* d_in, const int* in_sizes, int n_in,
                              void* d_out, int out_size)
{
    const float* logits = (const float*)d_in[0];
    const float* iW0 = (const float*)d_in[2];
    const float* ib0 = (const float*)d_in[3];
    const float* iW1 = (const float*)d_in[4];
    const float* ib1 = (const float*)d_in[5];
    const float* iW2 = (const float*)d_in[6];
    const float* ib2 = (const float*)d_in[7];
    const float* iW3 = (const float*)d_in[8];
    const float* ib3 = (const float*)d_in[9];
    const float* hb0 = (const float*)d_in[11];
    const float* hW1 = (const float*)d_in[12];
    const float* hb1 = (const float*)d_in[13];
    const float* hW2 = (const float*)d_in[14];
    const float* hb2 = (const float*)d_in[15];
    const float* hW3 = (const float*)d_in[16];
    const float* hb3 = (const float*)d_in[17];

    float* out = (float*)d_out;

    void *dz_addr = nullptr, *x2_addr = nullptr;
    cudaGetSymbolAddress(&dz_addr, g_dz);
    cudaGetSymbolAddress(&x2_addr, g_x2);
    float* dz = (float*)dz_addr;
    float* x2 = (float*)x2_addr;

    cudaFuncSetAttribute(mlp_tc, cudaFuncAttributeMaxDynamicSharedMemorySize, SMEM_ALLOC);

    // 1) constants (4 parallel blocks)
    setup_kernel<<<4, 128>>>(hb0, hW1, hb1, hW2, hb2, hW3, hb3);

    // 2) networks 0 and 1 on x1 = logits (2 CTAs/SM resident)
    dim3 g1(148, 2);
    mlp_tc<<<g1, MLP_T, SMEM_ALLOC>>>(logits, 0,
                                      iW0, ib0, iW1, ib1, iW2, ib2, iW3, ib3, dz);

    // 3) reduce k=0 -> x2 ; k=1 -> y1
    const int RWARPS = 8;
    dim3 gr((NS + RWARPS - 1) / RWARPS);
    reduce_kernel<<<gr, RWARPS * 32>>>(dz + 0 * (size_t)ROWSK, logits, 0, x2);
    reduce_kernel<<<gr, RWARPS * 32>>>(dz + 1 * (size_t)ROWSK, logits, 1, out);

    // 4) network 2 on x2 (fill both CTA slots per SM)
    dim3 g2(296, 1);
    mlp_tc<<<g2, MLP_T, SMEM_ALLOC>>>(x2, 2,
                                      iW0, ib0, iW1, ib1, iW2, ib2, iW3, ib3, dz);

    // 5) reduce k=2 -> y2
    reduce_kernel<<<gr, RWARPS * 32>>>(dz + 2 * (size_t)ROWSK, x2, 2, out + NS);

    // 6) pass-through logits
    cudaMemcpyAsync(out + 2 * NS, logits, NS * sizeof(float), cudaMemcpyDeviceToDevice);
}

// round 13
// speedup vs baseline: 7.9816x; 1.0516x over previous
#include <cuda_runtime.h>
#include <cuda_fp16.h>
#include <math.h>
#include <stdint.h>

#define NS 16384
#define NB 100
#define NQ 101
#define HID 100
#define ROWSK (NS * NQ)        // 1654784
#define TILEM 128
#define NTILES (ROWSK / TILEM) // 12928 exactly
#define NKC 6                  // full k16 chunks; +1 k8 tail at col 96
#define PITCH 240              // bytes per smem row (112*2 + 16 pad) -> LDSM conflict-free
#define MLP_T 256

typedef unsigned int u32;

// ---- smem layout (byte offsets) ---------------------------------------------
#define AB (TILEM * PITCH)         // 30720
#define OFF_A    0
#define OFF_W1   (AB)
#define OFF_W2   (2 * AB)
#define OFF_RED  (3 * AB)          // 2 parity buffers x 2048 B
#define OFF_VEC  (OFF_RED + 4096)  // b1[128] b2[128] w3[128] (floats)
#define OFF_W0H  (OFF_VEC + 3 * 128 * 4)  // w0 half2[64], b0 half2[64] = 512 B
#define SMEM_ALLOC (OFF_W0H + 512 + 256)  // ~98 KB -> 2 CTAs/SM

// ---------------- device globals (scratch) -----------------------------------
__device__ float g_ccw[NQ];
__device__ float g_csc[NQ];
__device__ float g_oh[3][2];
__device__ float g_dz[3][ROWSK];
__device__ float g_x2[NS];

// ---------------- PTX helpers (base-ISA only: ldmatrix + mma.sync) -----------
__device__ __forceinline__ u32 smem_u32(const void* p) {
    u32 a;
    asm("{ .reg .u64 t; cvta.to.shared.u64 t, %1; cvt.u32.u64 %0, t; }" : "=r"(a) : "l"(p));
    return a;
}
__device__ __forceinline__ void ldsm4(u32* r, u32 a) {
    asm volatile("ldmatrix.sync.aligned.m8n8.x4.shared.b16 {%0,%1,%2,%3}, [%4];"
                 : "=r"(r[0]), "=r"(r[1]), "=r"(r[2]), "=r"(r[3]) : "r"(a));
}
__device__ __forceinline__ void ldsm2(u32* r, u32 a) {
    asm volatile("ldmatrix.sync.aligned.m8n8.x2.shared.b16 {%0,%1}, [%2];"
                 : "=r"(r[0]), "=r"(r[1]) : "r"(a));
}
__device__ __forceinline__ void ldsm1(u32* r, u32 a) {
    asm volatile("ldmatrix.sync.aligned.m8n8.x1.shared.b16 {%0}, [%1];"
                 : "=r"(r[0]) : "r"(a));
}
__device__ __forceinline__ void mma16816(float* c, const u32* a, const u32* b) {
    asm volatile("mma.sync.aligned.m16n8k16.row.col.f32.f16.f16.f32 "
                 "{%0,%1,%2,%3}, {%4,%5,%6,%7}, {%8,%9}, {%0,%1,%2,%3};"
                 : "+f"(c[0]), "+f"(c[1]), "+f"(c[2]), "+f"(c[3])
                 : "r"(a[0]), "r"(a[1]), "r"(a[2]), "r"(a[3]), "r"(b[0]), "r"(b[1]));
}
__device__ __forceinline__ void mma1688(float* c, const u32* a, const u32* b) {
    asm volatile("mma.sync.aligned.m16n8k8.row.col.f32.f16.f16.f32 "
                 "{%0,%1,%2,%3}, {%4,%5}, {%6}, {%0,%1,%2,%3};"
                 : "+f"(c[0]), "+f"(c[1]), "+f"(c[2]), "+f"(c[3])
                 : "r"(a[0]), "r"(a[1]), "r"(b[0]));
}
// half-CTA barrier: 128 threads of one wm group (threads 0-127 or 128-255)
__device__ __forceinline__ void bar_half(int wm) {
    asm volatile("bar.sync %0, 128;" :: "r"(1 + wm) : "memory");
}

__device__ __forceinline__ unsigned short h_bits(float f) {
    __half h = __float2half_rn(f);
    return *reinterpret_cast<unsigned short*>(&h);
}
__device__ __forceinline__ u32 pack_hi(float f0, float f1) {
    return (u32)h_bits(f0) | ((u32)h_bits(f1) << 16);
}

// ---------------- setup: 4 blocks (CC quadrature + 3x oh constants) ----------
__global__ void setup_kernel(const float* __restrict__ hb0,
                             const float* __restrict__ hW1,
                             const float* __restrict__ hb1,
                             const float* __restrict__ hW2,
                             const float* __restrict__ hb2,
                             const float* __restrict__ hW3,
                             const float* __restrict__ hb3)
{
    const double PI = 3.14159265358979323846;
    int t = threadIdx.x;

    if (blockIdx.x == 0) {
        if (t < NQ) {
            double acc = 0.0;
            for (int i = 0; i <= NB; i++) {
                double lij = cos((double)i * (double)t * PI / (double)NB);
                if (t == 0)  lij = 0.5;
                if (t == NB) lij *= 0.5;
                double Wi;
                if (i == 0)      Wi = 1.0;
                else if (i & 1)  Wi = 0.0;
                else             Wi = 2.0 / (1.0 - (double)i * (double)i);
                acc += lij * Wi;
            }
            g_ccw[t] = (float)(acc * 2.0 / (double)NB);
            g_csc[t] = (float)((cos((double)t * PI / (double)NB) + 1.0) * 0.5);
        }
        return;
    }

    int k = blockIdx.x - 1;
    __shared__ float hA[HID], hB[HID];
    if (t < HID) hA[t] = fmaxf(hb0[k * HID + t], 0.f);
    __syncthreads();
    if (t < HID) {
        float s = hb1[k * HID + t];
        for (int i = 0; i < HID; i++) s += hW1[(k * HID + t) * HID + i] * hA[i];
        hB[t] = fmaxf(s, 0.f);
    }
    __syncthreads();
    if (t < HID) {
        float s = hb2[k * HID + t];
        for (int i = 0; i < HID; i++) s += hW2[(k * HID + t) * HID + i] * hB[i];
        hA[t] = fmaxf(s, 0.f);
    }
    __syncthreads();
    if (t < 2) {
        float s = hb3[k * 2 + t];
        for (int i = 0; i < HID; i++) s += hW3[(k * 2 + t) * HID + i] * hA[i];
        g_oh[k][t] = s;
    }
}

// ---------------- tensor-core MLP kernel (fp16 mma.sync, 2 CTAs/SM) ----------
__global__ __launch_bounds__(MLP_T, 2)
void mlp_tc(const float* __restrict__ xin, int kbase,
            const float* __restrict__ iW0, const float* __restrict__ ib0,
            const float* __restrict__ iW1, const float* __restrict__ ib1,
            const float* __restrict__ iW2, const float* __restrict__ ib2,
            const float* __restrict__ iW3, const float* __restrict__ ib3,
            float* __restrict__ dzbase)
{
    extern __shared__ char ab[];
    const u32 sm = smem_u32(ab);

    const int tid  = threadIdx.x;
    const int lane = tid & 31;
    const int wid  = tid >> 5;
    const int wm   = wid >> 2;   // 0..1  (M group; threads [wm*128, wm*128+128))
    const int wn   = wid & 3;    // 0..3  (SMSP index)
    const int k    = kbase + blockIdx.y;

    // zero A + W buffers (establishes K/N pads)
    for (int i = tid; i < (3 * AB) / 16; i += MLP_T)
        reinterpret_cast<uint4*>(ab)[i] = make_uint4(0, 0, 0, 0);

    float*   redv = (float*)(ab + OFF_RED);   // [2][128][4]
    float*   b1v  = (float*)(ab + OFF_VEC);
    float*   b2v  = b1v + 128;
    float*   w3v  = b2v + 128;
    __half2* w0h  = (__half2*)(ab + OFF_W0H); // [64]
    __half2* b0h  = w0h + 64;                 // [64]
    __syncthreads();

    for (int i = tid; i < 128; i += MLP_T) {
        b1v[i] = (i < HID) ? ib1[k * HID + i] : 0.f;
        b2v[i] = (i < HID) ? ib2[k * HID + i] : 0.f;
        w3v[i] = (i < HID) ? iW3[k * HID + i] : 0.f;
    }
    if (tid < 64) {
        int c0 = 2 * tid, c1 = 2 * tid + 1;
        float w0a = (c0 < HID) ? iW0[(k * HID + c0) * 3] : 0.f;  // h==0: input col 0 only
        float w0b = (c1 < HID) ? iW0[(k * HID + c1) * 3] : 0.f;
        float b0a = (c0 < HID) ? ib0[k * HID + c0] : 0.f;
        float b0b = (c1 < HID) ? ib0[k * HID + c1] : 0.f;
        w0h[tid] = __floats2half2_rn(w0a, w0b);
        b0h[tid] = __floats2half2_rn(b0a, b0b);
    }
    // stage W1/W2 (fp16) as [N][K], pitch 240B
    for (int idx = tid; idx < HID * HID; idx += MLP_T) {
        int o = idx / HID, i = idx % HID;
        u32 off = o * PITCH + i * 2;
        *(unsigned short*)(ab + OFF_W1 + off) = h_bits(iW1[(k * HID + o) * HID + i]);
        *(unsigned short*)(ab + OFF_W2 + off) = h_bits(iW2[(k * HID + o) * HID + i]);
    }
    __syncthreads();

    // lane-dependent ldmatrix address terms
    const u32 a_l  = (u32)((lane & 15) * PITCH + ((lane >> 4) & 1) * 16);  // k16 A (x4)
    const u32 a_l2 = (u32)((lane & 15) * PITCH + 192);                     // k8 tail A (x2)
    const u32 b_l  = (u32)((lane & 7) * PITCH + ((lane >> 3) & 1) * 16);   // k16 B (x2)
    const u32 b_l1 = (u32)((lane & 7) * PITCH + 192);                      // k8 tail B (x1)
    const u32 sA = sm + OFF_A;

    const float b3 = ib3[k];
    const __half2 hz = __float2half2_rn(0.f);

    int par = 0;
    for (int tile = blockIdx.x; tile < NTILES; tile += gridDim.x, par ^= 1) {
        float* redp = redv + par * 512;

        // ---- layer 0: scalar -> 100, packed half2 math, vector stores ----
        {
            int r0 = tid >> 1;
            int row = tile * TILEM + r0;
            int n = row / NQ, j = row - n * NQ;
            __half2 s2 = __float2half2_rn(xin[n] * g_csc[j]);
            char* a0 = ab + OFF_A + r0 * PITCH;
            if ((tid & 1) == 0) {
                // cols 0..47: pairs 0..23, 6 x STS.128
                #pragma unroll
                for (int q = 0; q < 6; q++) {
                    u32 t0[4];
                    #pragma unroll
                    for (int e = 0; e < 4; e++) {
                        __half2 v = __hmax2(__hfma2(w0h[q * 4 + e], s2, b0h[q * 4 + e]), hz);
                        t0[e] = *(u32*)&v;
                    }
                    *(uint4*)(a0 + q * 16) = make_uint4(t0[0], t0[1], t0[2], t0[3]);
                }
            } else {
                // cols 48..95: pairs 24..47, 6 x STS.128; cols 96..99: pairs 48..49, STS.64
                #pragma unroll
                for (int q = 0; q < 6; q++) {
                    u32 t0[4];
                    #pragma unroll
                    for (int e = 0; e < 4; e++) {
                        __half2 v = __hmax2(__hfma2(w0h[24 + q * 4 + e], s2, b0h[24 + q * 4 + e]), hz);
                        t0[e] = *(u32*)&v;
                    }
                    *(uint4*)(a0 + 96 + q * 16) = make_uint4(t0[0], t0[1], t0[2], t0[3]);
                }
                __half2 v0 = __hmax2(__hfma2(w0h[48], s2, b0h[48]), hz);
                __half2 v1 = __hmax2(__hfma2(w0h[49], s2, b0h[49]), hz);
                *(uint2*)(a0 + 192) = make_uint2(*(u32*)&v0, *(u32*)&v1);
            }
        }
        bar_half(wm);   // rows of this half ready for this half's ldsm

        // ---- layers 1 & 2 via mma.sync ----
        for (int L = 0; L < 2; L++) {
            const u32 sW = sm + (L ? OFF_W2 : OFF_W1);

            // rotated N-partition for SMSP balance
            const int part = (wn + wm + 2 * L) & 3;
            const int nt0  = (part == 0) ? 0 : (1 + 3 * part);
            const int ncnt = (part == 0) ? 4 : 3;

            float acc[4][4][4];
            #pragma unroll
            for (int mi = 0; mi < 4; mi++)
                #pragma unroll
                for (int ni = 0; ni < 4; ni++)
                    #pragma unroll
                    for (int e = 0; e < 4; e++) acc[mi][ni][e] = 0.f;

            #pragma unroll
            for (int kc = 0; kc < NKC; kc++) {
                u32 ah[4][4], bh[4][2];
                #pragma unroll
                for (int mi = 0; mi < 4; mi++) {
                    u32 aoff = (u32)((wm * 4 + mi) * (16 * PITCH) + kc * 32) + a_l;
                    ldsm4(ah[mi], sA + aoff);
                }
                #pragma unroll
                for (int ni = 0; ni < 4; ni++) {
                    if (ni < ncnt) {
                        u32 boff = (u32)((nt0 + ni) * (8 * PITCH) + kc * 32) + b_l;
                        ldsm2(bh[ni], sW + boff);
                    }
                }
                #pragma unroll
                for (int mi = 0; mi < 4; mi++)
                    #pragma unroll
                    for (int ni = 0; ni < 4; ni++)
                        if (ni < ncnt)
                            mma16816(acc[mi][ni], ah[mi], bh[ni]);
            }
            // k8 tail: cols 96..103 (100..103 are zero padding)
            {
                u32 at[4][2], bt[4][1];
                #pragma unroll
                for (int mi = 0; mi < 4; mi++) {
                    u32 aoff = (u32)((wm * 4 + mi) * (16 * PITCH)) + a_l2;
                    ldsm2(at[mi], sA + aoff);
                }
                #pragma unroll
                for (int ni = 0; ni < 4; ni++) {
                    if (ni < ncnt) {
                        u32 boff = (u32)((nt0 + ni) * (8 * PITCH)) + b_l1;
                        ldsm1(bt[ni], sW + boff);
                    }
                }
                #pragma unroll
                for (int mi = 0; mi < 4; mi++)
                    #pragma unroll
                    for (int ni = 0; ni < 4; ni++)
                        if (ni < ncnt)
                            mma1688(acc[mi][ni], at[mi], bt[ni]);
            }

            if (L == 0) {
                bar_half(wm);   // this half's A reads complete before overwrite
                // epilogue: bias + relu, fp16, write back to A (own half rows)
                #pragma unroll
                for (int mi = 0; mi < 4; mi++) {
                    int r0 = (wm * 4 + mi) * 16 + (lane >> 2);
                    #pragma unroll
                    for (int ni = 0; ni < 4; ni++) {
                        int c0 = (nt0 + ni) * 8 + (lane & 3) * 2;
                        if (ni < ncnt && c0 < HID) {
                            float bb0 = b1v[c0], bb1 = b1v[c0 + 1];
                            float v0 = fmaxf(acc[mi][ni][0] + bb0, 0.f);
                            float v1 = fmaxf(acc[mi][ni][1] + bb1, 0.f);
                            float v2 = fmaxf(acc[mi][ni][2] + bb0, 0.f);
                            float v3 = fmaxf(acc[mi][ni][3] + bb1, 0.f);
                            *(u32*)(ab + OFF_A + r0 * PITCH + c0 * 2)       = pack_hi(v0, v1);
                            *(u32*)(ab + OFF_A + (r0 + 8) * PITCH + c0 * 2) = pack_hi(v2, v3);
                        }
                    }
                }
                bar_half(wm);   // A ready for this half's L2 ldsm
            } else {
                // layer 3: weighted partial dot per thread, warp shfl, smem reduce
                float rp[4][2];
                #pragma unroll
                for (int mi = 0; mi < 4; mi++) { rp[mi][0] = 0.f; rp[mi][1] = 0.f; }
                #pragma unroll
                for (int ni = 0; ni < 4; ni++) {
                    int c0 = (nt0 + ni) * 8 + (lane & 3) * 2;
                    if (ni < ncnt && c0 < HID) {
                        float bb0 = b2v[c0], bb1 = b2v[c0 + 1];
                        float w30 = w3v[c0], w31 = w3v[c0 + 1];
                        #pragma unroll
                        for (int mi = 0; mi < 4; mi++) {
                            float v0 = fmaxf(acc[mi][ni][0] + bb0, 0.f);
                            float v1 = fmaxf(acc[mi][ni][1] + bb1, 0.f);
                            float v2 = fmaxf(acc[mi][ni][2] + bb0, 0.f);
                            float v3 = fmaxf(acc[mi][ni][3] + bb1, 0.f);
                            rp[mi][0] = fmaf(w30, v0, fmaf(w31, v1, rp[mi][0]));
                            rp[mi][1] = fmaf(w30, v2, fmaf(w31, v3, rp[mi][1]));
                        }
                    }
                }
                #pragma unroll
                for (int mi = 0; mi < 4; mi++) {
                    #pragma unroll
                    for (int e = 0; e < 2; e++) {
                        rp[mi][e] += __shfl_xor_sync(0xffffffffu, rp[mi][e], 1);
                        rp[mi][e] += __shfl_xor_sync(0xffffffffu, rp[mi][e], 2);
                    }
                }
                if ((lane & 3) == 0) {
                    #pragma unroll
                    for (int mi = 0; mi < 4; mi++) {
                        int r0 = (wm * 4 + mi) * 16 + (lane >> 2);
                        redp[r0 * 4 + wn] = rp[mi][0];
                        redp[(r0 + 8) * 4 + wn] = rp[mi][1];
                    }
                }
                __syncthreads();   // redv complete; also: all A reads of this tile done
                if (tid < TILEM) {
                    int row = tile * TILEM + tid;
                    int j = row % NQ;
                    float out = redp[tid * 4] + redp[tid * 4 + 1]
                              + redp[tid * 4 + 2] + redp[tid * 4 + 3] + b3;
                    float dz = (out > 0.f) ? (out + 1.f) : expf(out);
                    dzbase[(size_t)k * ROWSK + row] = dz * g_ccw[j];
                }
                // no trailing sync: redv parity buffer protects reuse
            }
        }
    }
}

// ---------------- reduction: warp per sample; blockIdx.y picks stream --------
__global__ void reduce_pair(const float* __restrict__ dzA, const float* __restrict__ xA,
                            int kA, float* __restrict__ dstA,
                            const float* __restrict__ dzB, const float* __restrict__ xB,
                            int kB, float* __restrict__ dstB)
{
    const float* dzk = (blockIdx.y == 0) ? dzA : dzB;
    const float* xin = (blockIdx.y == 0) ? xA : xB;
    float* dst       = (blockIdx.y == 0) ? dstA : dstB;
    int k            = (blockIdx.y == 0) ? kA : kB;

    int n = blockIdx.x * (blockDim.x >> 5) + (threadIdx.x >> 5);
    int lane = threadIdx.x & 31;
    if (n >= NS) return;
    const float* p = dzk + (size_t)n * NQ;
    float s = 0.f;
    for (int j = lane; j < NQ; j += 32) s += p[j];
    #pragma unroll
    for (int o = 16; o; o >>= 1) s += __shfl_xor_sync(0xffffffffu, s, o);
    if (lane == 0) {
        float z = s * xin[n] * 0.5f;
        dst[n] = expf(g_oh[k][1]) * z + g_oh[k][0];
    }
}

// ---------------- launch -----------------------------------------------------
extern "C" void kernel_launch(void* const* d_in, const int* in_sizes, int n_in,
                              void* d_out, int out_size)
{
    const float* logits = (const float*)d_in[0];
    const float* iW0 = (const float*)d_in[2];
    const float* ib0 = (const float*)d_in[3];
    const float* iW1 = (const float*)d_in[4];
    const float* ib1 = (const float*)d_in[5];
    const float* iW2 = (const float*)d_in[6];
    const float* ib2 = (const float*)d_in[7];
    const float* iW3 = (const float*)d_in[8];
    const float* ib3 = (const float*)d_in[9];
    const float* hb0 = (const float*)d_in[11];
    const float* hW1 = (const float*)d_in[12];
    const float* hb1 = (const float*)d_in[13];
    const float* hW2 = (const float*)d_in[14];
    const float* hb2 = (const float*)d_in[15];
    const float* hW3 = (const float*)d_in[16];
    const float* hb3 = (const float*)d_in[17];

    float* out = (float*)d_out;

    void *dz_addr = nullptr, *x2_addr = nullptr;
    cudaGetSymbolAddress(&dz_addr, g_dz);
    cudaGetSymbolAddress(&x2_addr, g_x2);
    float* dz = (float*)dz_addr;
    float* x2 = (float*)x2_addr;

    cudaFuncSetAttribute(mlp_tc, cudaFuncAttributeMaxDynamicSharedMemorySize, SMEM_ALLOC);

    // 1) constants (4 parallel blocks)
    setup_kernel<<<4, 128>>>(hb0, hW1, hb1, hW2, hb2, hW3, hb3);

    // 2) networks 0 and 1 on x1 = logits (2 CTAs/SM resident)
    dim3 g1(148, 2);
    mlp_tc<<<g1, MLP_T, SMEM_ALLOC>>>(logits, 0,
                                      iW0, ib0, iW1, ib1, iW2, ib2, iW3, ib3, dz);

    // 3) fused reduce: k=0 -> x2 and k=1 -> y1
    const int RWARPS = 8;
    dim3 gr((NS + RWARPS - 1) / RWARPS, 2);
    reduce_pair<<<gr, RWARPS * 32>>>(dz + 0 * (size_t)ROWSK, logits, 0, x2,
                                     dz + 1 * (size_t)ROWSK, logits, 1, out);

    // 4) network 2 on x2 (fill both CTA slots per SM)
    dim3 g2(296, 1);
    mlp_tc<<<g2, MLP_T, SMEM_ALLOC>>>(x2, 2,
                                      iW0, ib0, iW1, ib1, iW2, ib2, iW3, ib3, dz);

    // 5) reduce k=2 -> y2 (single stream via same kernel, both halves identical)
    dim3 gr2((NS + RWARPS - 1) / RWARPS, 1);
    reduce_pair<<<gr2, RWARPS * 32>>>(dz + 2 * (size_t)ROWSK, x2, 2, out + NS,
                                      dz + 2 * (size_t)ROWSK, x2, 2, out + NS);

    // 6) pass-through logits
    cudaMemcpyAsync(out + 2 * NS, logits, NS * sizeof(float), cudaMemcpyDeviceToDevice);
}